// round 10
// baseline (speedup 1.0000x reference)
#include <cuda_runtime.h>

// B=32, R=64 (theta j, phi p), L=32, M=63, spins=2, C=64. All inputs f32.
#define TWO_PI_F 6.28318530717958647692f

#define SZ_SPHERE 16777216
#define SZ_KERNEL 524288
#define SZ_LEG    258048
#define SZ_W      64

// Packed (l,m): row(l,b,mm) = 32*l*l + b*(2l+1) + mm, mm = m-31+l in [0,2l].
#define N_A 4194304            // 32768*128 float2
#define N_G 16515072           // 126 MiB: G (b,i,m,j,c) then reused as H (b,j,o,m,d)

__device__ float2 g_G   [N_G];
__device__ float2 g_Ain [N_A];
__device__ float2 g_Aout[N_A];

typedef unsigned long long ull;

__device__ __forceinline__ ull pk2(float lo, float hi) {
    ull r; asm("mov.b64 %0, {%1,%2};" : "=l"(r) : "f"(lo), "f"(hi)); return r;
}
__device__ __forceinline__ ull ffma2(ull a, ull b, ull c) {
    ull d; asm("fma.rn.f32x2 %0, %1, %2, %3;" : "=l"(d) : "l"(a), "l"(b), "l"(c)); return d;
}
__device__ __forceinline__ float2 upk2(ull v) {
    float2 f; asm("mov.b64 {%0,%1}, %2;" : "=f"(f.x), "=f"(f.y) : "l"(v)); return f;
}
__device__ __forceinline__ float2 pq(ull P, ull Q) {
    float2 p = upk2(P), q = upk2(Q);
    return make_float2(p.x - q.y, p.y + q.x);
}

// ---------------------------------------------------------------------------
// FFT-64: radix-2 DIF, natural input -> bit-reversed output.
// ---------------------------------------------------------------------------
__constant__ float cW[32] = {
    1.0f, 0.99518472667f, 0.98078528040f, 0.95694033573f,
    0.92387953251f, 0.88192126435f, 0.83146961230f, 0.77301045336f,
    0.70710678119f, 0.63439328416f, 0.55557023302f, 0.47139673683f,
    0.38268343236f, 0.29028467725f, 0.19509032202f, 0.09801714033f,
    0.0f, -0.09801714033f, -0.19509032202f, -0.29028467725f,
    -0.38268343236f, -0.47139673683f, -0.55557023302f, -0.63439328416f,
    -0.70710678119f, -0.77301045336f, -0.83146961230f, -0.88192126435f,
    -0.92387953251f, -0.95694033573f, -0.98078528040f, -0.99518472667f };
__constant__ float sW[32] = {
    0.0f, 0.09801714033f, 0.19509032202f, 0.29028467725f,
    0.38268343236f, 0.47139673683f, 0.55557023302f, 0.63439328416f,
    0.70710678119f, 0.77301045336f, 0.83146961230f, 0.88192126435f,
    0.92387953251f, 0.95694033573f, 0.98078528040f, 0.99518472667f,
    1.0f, 0.99518472667f, 0.98078528040f, 0.95694033573f,
    0.92387953251f, 0.88192126435f, 0.83146961230f, 0.77301045336f,
    0.70710678119f, 0.63439328416f, 0.55557023302f, 0.47139673683f,
    0.38268343236f, 0.29028467725f, 0.19509032202f, 0.09801714033f };

__device__ __forceinline__ constexpr int bitrev6(int i) {
    return ((i & 1) << 5) | ((i & 2) << 3) | ((i & 4) << 1)
         | ((i & 8) >> 1) | ((i & 16) >> 3) | ((i & 32) >> 5);
}

template <int LEN, bool INV>
__device__ __forceinline__ void fft_stage(float2* x) {
    constexpr int HALF = LEN / 2;
    constexpr int STEP = 64 / LEN;
    #pragma unroll
    for (int st = 0; st < 64; st += LEN) {
        #pragma unroll
        for (int k = 0; k < HALF; k++) {
            float2 u = x[st + k], v = x[st + k + HALF];
            x[st + k] = make_float2(u.x + v.x, u.y + v.y);
            float2 t = make_float2(u.x - v.x, u.y - v.y);
            if (k == 0) {
                x[st + k + HALF] = t;
            } else {
                float wr = cW[k * STEP];
                float wi = INV ? sW[k * STEP] : -sW[k * STEP];
                x[st + k + HALF] = make_float2(t.x * wr - t.y * wi,
                                               t.x * wi + t.y * wr);
            }
        }
    }
}

template <bool INV>
__device__ __forceinline__ void fft64(float2* x) {
    fft_stage<64, INV>(x);
    fft_stage<32, INV>(x);
    fft_stage<16, INV>(x);
    fft_stage<8,  INV>(x);
    fft_stage<4,  INV>(x);
    fft_stage<2,  INV>(x);
}

// ---------------------------------------------------------------------------
// k1: forward FFT over phi. G[b,i,m,j,c] = X[(m-31)&63]/64, X = fft_p(f).
// ---------------------------------------------------------------------------
__global__ void k1_fft(const float* __restrict__ fre, const float* __restrict__ fim) {
    int bid = blockIdx.x;
    int j = bid & 63, bi = bid >> 6;
    int i = bi & 1,  b = bi >> 1;
    int c = threadIdx.x;   // 0..63

    long base = (long)(b * 64 + j) * 8192 + i * 64 + c;   // + p*128
    float2 x[64];
    #pragma unroll
    for (int p = 0; p < 64; p++) {
        long a = base + (long)p * 128;
        x[p] = make_float2(fre[a] * (1.0f / 64.0f), fim[a] * (1.0f / 64.0f));
    }
    fft64<false>(x);

    long gb = (long)bi * 63 * 4096 + (long)j * 64 + c;
    #pragma unroll
    for (int r = 0; r < 64; r++) {
        int k = bitrev6(r);
        if (k != 32) {                       // m==63 bin doesn't exist
            int m = (k + 31) & 63;
            g_G[gb + (long)m * 4096] = x[r];
        }
    }
}

// ---------------------------------------------------------------------------
// k2: theta quadrature, packed output. Register-blocked 4c x 2l, FFMA2.
// A_in[row(l,b,mm), i*64+c] = sum_j (2pi w_j leg_in[i,l,m,j]) G[b,i,m,j,c]
// ---------------------------------------------------------------------------
__global__ void k2_theta(const float* __restrict__ leg_in, const float* __restrict__ w) {
    __shared__ float2 sh_g[64][64];   // [j][c]    32 KB
    __shared__ ull    sh_P[32][65];   // [l][j] dup (p,p), padded  16.6 KB

    int m = blockIdx.x, i = blockIdx.y, b = blockIdx.z;
    int tid = threadIdx.x;
    int bi = b * 2 + i;

    long gbase = ((long)bi * 63 + m) * 4096;
    for (int e = tid; e < 4096; e += 256) sh_g[e >> 6][e & 63] = g_G[gbase + e];
    for (int e = tid; e < 2048; e += 256) {
        int l = e >> 6, jj = e & 63;
        float pl = TWO_PI_F * w[jj] * leg_in[((i * 32 + l) * 63 + m) * 64 + jj];
        sh_P[l][jj] = pk2(pl, pl);
    }
    __syncthreads();

    int cq = tid & 15, lg = tid >> 4;   // c4 = 4*cq; lv = lg + 16*u (u<2)
    int c4 = cq * 4;
    int lmin = (m <= 31) ? (31 - m) : (m - 31);
    int nv = 32 - lmin;

    ull acc[2][4];
    #pragma unroll
    for (int u = 0; u < 2; u++)
        #pragma unroll
        for (int cc = 0; cc < 4; cc++) acc[u][cc] = 0ull;

    int l0 = lmin + lg, l1 = lmin + lg + 16;
    for (int jj = 0; jj < 64; jj++) {
        ulonglong2 gA = *(const ulonglong2*)&sh_g[jj][c4];
        ulonglong2 gB = *(const ulonglong2*)&sh_g[jj][c4 + 2];
        ull q0 = (l0 < 32) ? sh_P[l0][jj] : 0ull;
        ull q1 = (l1 < 32) ? sh_P[l1][jj] : 0ull;
        acc[0][0] = ffma2(q0, gA.x, acc[0][0]);
        acc[0][1] = ffma2(q0, gA.y, acc[0][1]);
        acc[0][2] = ffma2(q0, gB.x, acc[0][2]);
        acc[0][3] = ffma2(q0, gB.y, acc[0][3]);
        acc[1][0] = ffma2(q1, gA.x, acc[1][0]);
        acc[1][1] = ffma2(q1, gA.y, acc[1][1]);
        acc[1][2] = ffma2(q1, gB.x, acc[1][2]);
        acc[1][3] = ffma2(q1, gB.y, acc[1][3]);
    }
    #pragma unroll
    for (int u = 0; u < 2; u++) {
        int lv = lg + 16 * u;
        if (lv < nv) {
            int l = lmin + lv;
            int mm = (m - 31) + l;
            long row = (long)(32 * l * l) + b * (2 * l + 1) + mm;
            float2 r0 = upk2(acc[u][0]), r1 = upk2(acc[u][1]);
            float2 r2 = upk2(acc[u][2]), r3 = upk2(acc[u][3]);
            float4* dst = (float4*)&g_Ain[row * 128 + i * 64 + c4];
            dst[0] = make_float4(r0.x, r0.y, r1.x, r1.y);
            dst[1] = make_float4(r2.x, r2.y, r3.x, r3.y);
        }
    }
}

// ---------------------------------------------------------------------------
// k3: per-l complex GEMM on packed rows, P/Q split (unchanged — passing).
// ---------------------------------------------------------------------------
__global__ void k3_gemm(const float* __restrict__ kre, const float* __restrict__ kim) {
    __shared__ float2     sA[16][64];
    __shared__ ulonglong2 sB[16][64];

    int o = blockIdx.x, rt = blockIdx.y, l = blockIdx.z;
    int nrow = 32 * (2 * l + 1);
    int row0 = rt * 64;
    if (row0 >= nrow) return;

    int tid = threadIdx.x, tx = tid & 15, ty = tid >> 4;
    ull accP[4][4], accQ[4][4];
    #pragma unroll
    for (int ri = 0; ri < 4; ri++)
        #pragma unroll
        for (int ci = 0; ci < 4; ci++) { accP[ri][ci] = 0ull; accQ[ri][ci] = 0ull; }

    long Abase = (long)(32 * l * l) * 128;
    long wbase = (long)l * 16384 + (long)o * 4096;

    for (int k0 = 0; k0 < 128; k0 += 16) {
        #pragma unroll
        for (int t = 0; t < 4; t++) {
            int e = tid + t * 256;
            int rr = e >> 4, kk = e & 15;
            int grow = row0 + rr;
            float2 v = make_float2(0.0f, 0.0f);
            if (grow < nrow) v = g_Ain[Abase + (long)grow * 128 + k0 + kk];
            sA[kk][rr] = v;
        }
        #pragma unroll
        for (int t = 0; t < 4; t++) {
            int e = tid + t * 256;
            int kk = e >> 6, col = e & 63;
            int ic = k0 + kk;
            long a = wbase + (long)(ic >> 6) * 8192 + (ic & 63) * 64 + col;
            float br = kre[a], bim = kim[a];
            sB[kk][col] = make_ulonglong2(pk2(br, br), pk2(bim, bim));
        }
        __syncthreads();
        #pragma unroll
        for (int kk = 0; kk < 16; kk++) {
            ull av[4];
            ulonglong2 bq[4];
            #pragma unroll
            for (int u = 0; u < 4; u++) av[u] = *(const ull*)&sA[kk][ty + 16 * u];
            #pragma unroll
            for (int u = 0; u < 4; u++) bq[u] = sB[kk][tx + 16 * u];
            #pragma unroll
            for (int ri = 0; ri < 4; ri++)
                #pragma unroll
                for (int ci = 0; ci < 4; ci++) {
                    accP[ri][ci] = ffma2(bq[ci].x, av[ri], accP[ri][ci]);
                    accQ[ri][ci] = ffma2(bq[ci].y, av[ri], accQ[ri][ci]);
                }
        }
        __syncthreads();
    }
    #pragma unroll
    for (int ri = 0; ri < 4; ri++) {
        int grow = row0 + ty + 16 * ri;
        if (grow < nrow) {
            #pragma unroll
            for (int ci = 0; ci < 4; ci++)
                g_Aout[Abase + (long)grow * 128 + o * 64 + tx + 16 * ci] =
                    pq(accP[ri][ci], accQ[ri][ci]);
        }
    }
}

// ---------------------------------------------------------------------------
// k4: inverse theta. Register-blocked 4d x 4j, FFMA2 dup table.
// H[b,j,o,m,d] = sum_{l>=lmin} leg_out[o,l,m,j] * A_out[row(l,b,m-31+l), o*64+d]
// ---------------------------------------------------------------------------
__global__ void k4_itheta(const float* __restrict__ leg_out) {
    __shared__ float2 sh_a[32][64];   // [l][d]   16 KB
    __shared__ ull    sh_Q[32][65];   // [l][j] dup (q,q), padded  16.6 KB

    int m = blockIdx.x, o = blockIdx.y, b = blockIdx.z;
    int tid = threadIdx.x;
    int lmin = (m <= 31) ? (31 - m) : (m - 31);

    for (int e = tid; e < 2048; e += 256) {
        int l = e >> 6, d = e & 63;
        float2 v = make_float2(0.0f, 0.0f);
        if (l >= lmin) {
            int mm = m - 31 + l;
            long row = (long)(32 * l * l) + b * (2 * l + 1) + mm;
            v = g_Aout[row * 128 + o * 64 + d];
        }
        sh_a[l][d] = v;
    }
    for (int e = tid; e < 2048; e += 256) {
        int l = e >> 6, j = e & 63;
        float q = leg_out[((o * 32 + l) * 63 + m) * 64 + j];
        sh_Q[l][j] = pk2(q, q);
    }
    __syncthreads();

    int cq = tid & 15, jg = tid >> 4;   // d4 = 4*cq; j = jg + 16*u (u<4)
    int d4 = cq * 4;

    ull acc[4][4];
    #pragma unroll
    for (int u = 0; u < 4; u++)
        #pragma unroll
        for (int cc = 0; cc < 4; cc++) acc[u][cc] = 0ull;

    for (int l = lmin; l < 32; l++) {
        ulonglong2 aA = *(const ulonglong2*)&sh_a[l][d4];
        ulonglong2 aB = *(const ulonglong2*)&sh_a[l][d4 + 2];
        ull a0 = aA.x, a1 = aA.y, a2 = aB.x, a3 = aB.y;
        #pragma unroll
        for (int u = 0; u < 4; u++) {
            ull qd = sh_Q[l][jg + 16 * u];
            acc[u][0] = ffma2(qd, a0, acc[u][0]);
            acc[u][1] = ffma2(qd, a1, acc[u][1]);
            acc[u][2] = ffma2(qd, a2, acc[u][2]);
            acc[u][3] = ffma2(qd, a3, acc[u][3]);
        }
    }
    #pragma unroll
    for (int u = 0; u < 4; u++) {
        int j = jg + 16 * u;
        long base = (long)((b * 64 + j) * 2 + o) * 4032 + m * 64 + d4;
        float2 r0 = upk2(acc[u][0]), r1 = upk2(acc[u][1]);
        float2 r2 = upk2(acc[u][2]), r3 = upk2(acc[u][3]);
        float4* dst = (float4*)&g_G[base];   // H
        dst[0] = make_float4(r0.x, r0.y, r1.x, r1.y);
        dst[1] = make_float4(r2.x, r2.y, r3.x, r3.y);
    }
}

// ---------------------------------------------------------------------------
// k5: inverse FFT over phi. X[(m-31)&63]=H[m], X[32]=0; out = invFFT (scaling
// cancels with the reference's /R * R).
// ---------------------------------------------------------------------------
__global__ void k5_ifft(void* __restrict__ dout, int mode, long out_cap) {
    int bid = blockIdx.x;             // matches k4's H layout
    int d = threadIdx.x;              // 0..63

    long hb = (long)bid * 4032 + d;
    float2 x[64];
    #pragma unroll
    for (int k = 0; k < 64; k++) {
        if (k == 32) x[k] = make_float2(0.0f, 0.0f);
        else {
            int m = (k + 31) & 63;
            x[k] = g_G[hb + (long)m * 64];
        }
    }
    fft64<true>(x);

    int o = bid & 1;
    long bj = (long)(bid >> 1);
    if (mode == 1) {
        float2* out2 = (float2*)dout;
        #pragma unroll
        for (int r = 0; r < 64; r++) {
            int p = bitrev6(r);
            long oi = ((bj * 64 + p) * 2 + o) * 64 + d;
            if (oi < out_cap) out2[oi] = x[r];
        }
    } else {
        float* out1 = (float*)dout;
        #pragma unroll
        for (int r = 0; r < 64; r++) {
            int p = bitrev6(r);
            long oi = ((bj * 64 + p) * 2 + o) * 64 + d;
            if (oi < out_cap) out1[oi] = x[r].x;    // real part
        }
    }
}

// ---------------------------------------------------------------------------
// Host dispatch (identical to the passing R6-R9 logic).
// ---------------------------------------------------------------------------
extern "C" void kernel_launch(void* const* d_in, const int* in_sizes, int n_in,
                              void* d_out, int out_size) {
    if (n_in < 7) return;

    const float* sph[2] = {0, 0};
    const float* ker[2] = {0, 0};
    const float* leg[2] = {0, 0};
    const float* w = 0;
    int ns = 0, nk = 0, nl = 0;

    for (int t = 0; t < n_in; t++) {
        const float* p = (const float*)d_in[t];
        int sz = in_sizes[t];
        if (sz == SZ_SPHERE && ns < 2) sph[ns++] = p;
        else if (sz == SZ_KERNEL && nk < 2) ker[nk++] = p;
        else if (sz == SZ_LEG && nl < 2) leg[nl++] = p;
        else if (sz == SZ_W && !w) w = p;
    }
    if (ns != 2 || nk != 2 || nl != 2 || !w) return;

    bool alpha = (n_in == 7 &&
                  in_sizes[0] == SZ_KERNEL && in_sizes[1] == SZ_KERNEL &&
                  in_sizes[2] == SZ_LEG    && in_sizes[3] == SZ_LEG &&
                  in_sizes[4] == SZ_W      &&
                  in_sizes[5] == SZ_SPHERE && in_sizes[6] == SZ_SPHERE);

    const float *fre, *fim, *kre, *kim;
    if (alpha) { fim = sph[0]; fre = sph[1]; kim = ker[0]; kre = ker[1]; }
    else       { fre = sph[0]; fim = sph[1]; kre = ker[0]; kim = ker[1]; }
    const float* leg_in = leg[0];
    const float* leg_out = leg[1];

    int mode;
    long cap;
    if (out_size == 33554432)      { mode = 1; cap = 16777216; }   // float2 count
    else if (out_size == 16777216) { mode = 0; cap = 16777216; }   // float count
    else                           { mode = 0; cap = (long)out_size; }

    k1_fft   <<<4096, 64>>>(fre, fim);
    k2_theta <<<dim3(63, 2, 32), 256>>>(leg_in, w);
    k3_gemm  <<<dim3(2, 32, 32), 256>>>(kre, kim);
    k4_itheta<<<dim3(63, 2, 32), 256>>>(leg_out);
    k5_ifft  <<<4096, 64>>>(d_out, mode, cap);
}

// round 11
// speedup vs baseline: 1.0382x; 1.0382x over previous
#include <cuda_runtime.h>

// B=32, R=64 (theta j, phi p), L=32, M=63, spins=2, C=64. All inputs f32.
#define TWO_PI_F 6.28318530717958647692f

#define SZ_SPHERE 16777216
#define SZ_KERNEL 524288
#define SZ_LEG    258048
#define SZ_W      64

// Packed (l,m): row(l,b,mm) = 32*l*l + b*(2l+1) + mm, mm = m-31+l in [0,2l].
#define N_A 4194304            // 32768*128 float2
#define N_G 16515072           // 126 MiB: G (b,i,m,j,c) then reused as H (b,j,o,m,d)

__device__ float2 g_G   [N_G];
__device__ float2 g_Ain [N_A];
__device__ float2 g_Aout[N_A];

typedef unsigned long long ull;

__device__ __forceinline__ ull pk2(float lo, float hi) {
    ull r; asm("mov.b64 %0, {%1,%2};" : "=l"(r) : "f"(lo), "f"(hi)); return r;
}
__device__ __forceinline__ ull ffma2(ull a, ull b, ull c) {
    ull d; asm("fma.rn.f32x2 %0, %1, %2, %3;" : "=l"(d) : "l"(a), "l"(b), "l"(c)); return d;
}
__device__ __forceinline__ float2 upk2(ull v) {
    float2 f; asm("mov.b64 {%0,%1}, %2;" : "=f"(f.x), "=f"(f.y) : "l"(v)); return f;
}
__device__ __forceinline__ float2 pq(ull P, ull Q) {
    float2 p = upk2(P), q = upk2(Q);
    return make_float2(p.x - q.y, p.y + q.x);
}

// ---------------------------------------------------------------------------
// FFT-64: radix-2 DIF, natural input -> bit-reversed output.
// ---------------------------------------------------------------------------
__constant__ float cW[32] = {
    1.0f, 0.99518472667f, 0.98078528040f, 0.95694033573f,
    0.92387953251f, 0.88192126435f, 0.83146961230f, 0.77301045336f,
    0.70710678119f, 0.63439328416f, 0.55557023302f, 0.47139673683f,
    0.38268343236f, 0.29028467725f, 0.19509032202f, 0.09801714033f,
    0.0f, -0.09801714033f, -0.19509032202f, -0.29028467725f,
    -0.38268343236f, -0.47139673683f, -0.55557023302f, -0.63439328416f,
    -0.70710678119f, -0.77301045336f, -0.83146961230f, -0.88192126435f,
    -0.92387953251f, -0.95694033573f, -0.98078528040f, -0.99518472667f };
__constant__ float sW[32] = {
    0.0f, 0.09801714033f, 0.19509032202f, 0.29028467725f,
    0.38268343236f, 0.47139673683f, 0.55557023302f, 0.63439328416f,
    0.70710678119f, 0.77301045336f, 0.83146961230f, 0.88192126435f,
    0.92387953251f, 0.95694033573f, 0.98078528040f, 0.99518472667f,
    1.0f, 0.99518472667f, 0.98078528040f, 0.95694033573f,
    0.92387953251f, 0.88192126435f, 0.83146961230f, 0.77301045336f,
    0.70710678119f, 0.63439328416f, 0.55557023302f, 0.47139673683f,
    0.38268343236f, 0.29028467725f, 0.19509032202f, 0.09801714033f };

__device__ __forceinline__ constexpr int bitrev6(int i) {
    return ((i & 1) << 5) | ((i & 2) << 3) | ((i & 4) << 1)
         | ((i & 8) >> 1) | ((i & 16) >> 3) | ((i & 32) >> 5);
}

template <int LEN, bool INV>
__device__ __forceinline__ void fft_stage(float2* x) {
    constexpr int HALF = LEN / 2;
    constexpr int STEP = 64 / LEN;
    #pragma unroll
    for (int st = 0; st < 64; st += LEN) {
        #pragma unroll
        for (int k = 0; k < HALF; k++) {
            float2 u = x[st + k], v = x[st + k + HALF];
            x[st + k] = make_float2(u.x + v.x, u.y + v.y);
            float2 t = make_float2(u.x - v.x, u.y - v.y);
            if (k == 0) {
                x[st + k + HALF] = t;
            } else {
                float wr = cW[k * STEP];
                float wi = INV ? sW[k * STEP] : -sW[k * STEP];
                x[st + k + HALF] = make_float2(t.x * wr - t.y * wi,
                                               t.x * wi + t.y * wr);
            }
        }
    }
}

template <bool INV>
__device__ __forceinline__ void fft64(float2* x) {
    fft_stage<64, INV>(x);
    fft_stage<32, INV>(x);
    fft_stage<16, INV>(x);
    fft_stage<8,  INV>(x);
    fft_stage<4,  INV>(x);
    fft_stage<2,  INV>(x);
}

// ---------------------------------------------------------------------------
// k1: forward FFT over phi. G[b,i,m,j,c] = X[(m-31)&63]/64, X = fft_p(f).
// ---------------------------------------------------------------------------
__global__ void k1_fft(const float* __restrict__ fre, const float* __restrict__ fim) {
    int bid = blockIdx.x;
    int j = bid & 63, bi = bid >> 6;
    int i = bi & 1,  b = bi >> 1;
    int c = threadIdx.x;   // 0..63

    long base = (long)(b * 64 + j) * 8192 + i * 64 + c;   // + p*128
    float2 x[64];
    #pragma unroll
    for (int p = 0; p < 64; p++) {
        long a = base + (long)p * 128;
        x[p] = make_float2(fre[a] * (1.0f / 64.0f), fim[a] * (1.0f / 64.0f));
    }
    fft64<false>(x);

    long gb = (long)bi * 63 * 4096 + (long)j * 64 + c;
    #pragma unroll
    for (int r = 0; r < 64; r++) {
        int k = bitrev6(r);
        if (k != 32) {                       // m==63 bin doesn't exist
            int m = (k + 31) & 63;
            g_G[gb + (long)m * 4096] = x[r];
        }
    }
}

// ---------------------------------------------------------------------------
// k2: theta quadrature, packed output. FFMA2 dup table, paired LDS.128 loads.
// acc u owns l = lq*8+u (adjacent, even base -> 16B-aligned pairs).
// A_in[row(l,b,mm), i*64+c] = sum_j (2pi w_j leg_in[i,l,m,j]) G[b,i,m,j,c]
// ---------------------------------------------------------------------------
__global__ void k2_theta(const float* __restrict__ leg_in, const float* __restrict__ w) {
    __shared__ float2 sh_g[64][64];   // [j][c]    32 KB
    __shared__ ull    sh_P[64][32];   // [j][l] dup (p,p)  16 KB

    int m = blockIdx.x, i = blockIdx.y, b = blockIdx.z;
    int tid = threadIdx.x;
    int bi = b * 2 + i;

    long gbase = ((long)bi * 63 + m) * 4096;
    for (int e = tid; e < 4096; e += 256) sh_g[e >> 6][e & 63] = g_G[gbase + e];
    for (int e = tid; e < 2048; e += 256) {
        int l = e >> 6, jj = e & 63;     // coalesced gmem read
        float pl = TWO_PI_F * w[jj] * leg_in[((i * 32 + l) * 63 + m) * 64 + jj];
        sh_P[jj][l] = pk2(pl, pl);       // transposed store (pairs over l adjacent)
    }
    __syncthreads();

    int c = tid & 63, lq = tid >> 6;     // acc u: l = lq*8 + u, u < 8
    int lmin = (m <= 31) ? (31 - m) : (m - 31);
    int lb = lq * 8;

    ull acc[8];
    #pragma unroll
    for (int u = 0; u < 8; u++) acc[u] = 0ull;

    for (int jj = 0; jj < 64; jj++) {
        ull g = *(const ull*)&sh_g[jj][c];
        #pragma unroll
        for (int v = 0; v < 4; v++) {
            ulonglong2 qp = *(const ulonglong2*)&sh_P[jj][lb + 2 * v];
            acc[2 * v]     = ffma2(qp.x, g, acc[2 * v]);
            acc[2 * v + 1] = ffma2(qp.y, g, acc[2 * v + 1]);
        }
    }
    #pragma unroll
    for (int u = 0; u < 8; u++) {
        int l = lb + u;
        if (l >= lmin) {                 // invalid l have P==0 -> acc==0 anyway
            int mm = (m - 31) + l;
            long row = (long)(32 * l * l) + b * (2 * l + 1) + mm;
            g_Ain[row * 128 + i * 64 + c] = upk2(acc[u]);
        }
    }
}

// ---------------------------------------------------------------------------
// k3: per-l complex GEMM on packed rows, P/Q split (unchanged — passing).
// ---------------------------------------------------------------------------
__global__ void k3_gemm(const float* __restrict__ kre, const float* __restrict__ kim) {
    __shared__ float2     sA[16][64];
    __shared__ ulonglong2 sB[16][64];

    int o = blockIdx.x, rt = blockIdx.y, l = blockIdx.z;
    int nrow = 32 * (2 * l + 1);
    int row0 = rt * 64;
    if (row0 >= nrow) return;

    int tid = threadIdx.x, tx = tid & 15, ty = tid >> 4;
    ull accP[4][4], accQ[4][4];
    #pragma unroll
    for (int ri = 0; ri < 4; ri++)
        #pragma unroll
        for (int ci = 0; ci < 4; ci++) { accP[ri][ci] = 0ull; accQ[ri][ci] = 0ull; }

    long Abase = (long)(32 * l * l) * 128;
    long wbase = (long)l * 16384 + (long)o * 4096;

    for (int k0 = 0; k0 < 128; k0 += 16) {
        #pragma unroll
        for (int t = 0; t < 4; t++) {
            int e = tid + t * 256;
            int rr = e >> 4, kk = e & 15;
            int grow = row0 + rr;
            float2 v = make_float2(0.0f, 0.0f);
            if (grow < nrow) v = g_Ain[Abase + (long)grow * 128 + k0 + kk];
            sA[kk][rr] = v;
        }
        #pragma unroll
        for (int t = 0; t < 4; t++) {
            int e = tid + t * 256;
            int kk = e >> 6, col = e & 63;
            int ic = k0 + kk;
            long a = wbase + (long)(ic >> 6) * 8192 + (ic & 63) * 64 + col;
            float br = kre[a], bim = kim[a];
            sB[kk][col] = make_ulonglong2(pk2(br, br), pk2(bim, bim));
        }
        __syncthreads();
        #pragma unroll
        for (int kk = 0; kk < 16; kk++) {
            ull av[4];
            ulonglong2 bq[4];
            #pragma unroll
            for (int u = 0; u < 4; u++) av[u] = *(const ull*)&sA[kk][ty + 16 * u];
            #pragma unroll
            for (int u = 0; u < 4; u++) bq[u] = sB[kk][tx + 16 * u];
            #pragma unroll
            for (int ri = 0; ri < 4; ri++)
                #pragma unroll
                for (int ci = 0; ci < 4; ci++) {
                    accP[ri][ci] = ffma2(bq[ci].x, av[ri], accP[ri][ci]);
                    accQ[ri][ci] = ffma2(bq[ci].y, av[ri], accQ[ri][ci]);
                }
        }
        __syncthreads();
    }
    #pragma unroll
    for (int ri = 0; ri < 4; ri++) {
        int grow = row0 + ty + 16 * ri;
        if (grow < nrow) {
            #pragma unroll
            for (int ci = 0; ci < 4; ci++)
                g_Aout[Abase + (long)grow * 128 + o * 64 + tx + 16 * ci] =
                    pq(accP[ri][ci], accQ[ri][ci]);
        }
    }
}

// ---------------------------------------------------------------------------
// k4: inverse theta. R9 mapping (d = tid&63, 16 j-accs) but acc u owns
// j = jq*16+u so Q dup pairs load as one LDS.128 (8 instead of 16 per l).
// H[b,j,o,m,d] = sum_{l>=lmin} leg_out[o,l,m,j] * A_out[row(l,b,m-31+l), o*64+d]
// ---------------------------------------------------------------------------
__global__ void k4_itheta(const float* __restrict__ leg_out) {
    __shared__ float2 sh_a[32][64];   // [l][d]   16 KB
    __shared__ ull    sh_Q[32][64];   // [l][j] dup (q,q)  16 KB

    int m = blockIdx.x, o = blockIdx.y, b = blockIdx.z;
    int tid = threadIdx.x;
    int lmin = (m <= 31) ? (31 - m) : (m - 31);

    for (int e = tid; e < 2048; e += 256) {
        int l = e >> 6, d = e & 63;
        float2 v = make_float2(0.0f, 0.0f);
        if (l >= lmin) {
            int mm = m - 31 + l;
            long row = (long)(32 * l * l) + b * (2 * l + 1) + mm;
            v = g_Aout[row * 128 + o * 64 + d];
        }
        sh_a[l][d] = v;
    }
    for (int e = tid; e < 2048; e += 256) {
        int l = e >> 6, j = e & 63;
        float q = leg_out[((o * 32 + l) * 63 + m) * 64 + j];
        sh_Q[l][j] = pk2(q, q);
    }
    __syncthreads();

    int d = tid & 63, jq = tid >> 6;   // acc u: j = jq*16 + u, u < 16
    int jb = jq * 16;
    ull acc[16];
    #pragma unroll
    for (int u = 0; u < 16; u++) acc[u] = 0ull;

    for (int l = lmin; l < 32; l++) {
        ull a = *(const ull*)&sh_a[l][d];
        #pragma unroll
        for (int v = 0; v < 8; v++) {
            ulonglong2 qp = *(const ulonglong2*)&sh_Q[l][jb + 2 * v];
            acc[2 * v]     = ffma2(qp.x, a, acc[2 * v]);
            acc[2 * v + 1] = ffma2(qp.y, a, acc[2 * v + 1]);
        }
    }
    #pragma unroll
    for (int u = 0; u < 16; u++) {
        int j = jb + u;
        g_G[(long)((b * 64 + j) * 2 + o) * 4032 + m * 64 + d] = upk2(acc[u]);   // H
    }
}

// ---------------------------------------------------------------------------
// k5: inverse FFT over phi. X[(m-31)&63]=H[m], X[32]=0; out = invFFT.
// ---------------------------------------------------------------------------
__global__ void k5_ifft(void* __restrict__ dout, int mode, long out_cap) {
    int bid = blockIdx.x;             // matches k4's H layout
    int d = threadIdx.x;              // 0..63

    long hb = (long)bid * 4032 + d;
    float2 x[64];
    #pragma unroll
    for (int k = 0; k < 64; k++) {
        if (k == 32) x[k] = make_float2(0.0f, 0.0f);
        else {
            int m = (k + 31) & 63;
            x[k] = g_G[hb + (long)m * 64];
        }
    }
    fft64<true>(x);

    int o = bid & 1;
    long bj = (long)(bid >> 1);
    if (mode == 1) {
        float2* out2 = (float2*)dout;
        #pragma unroll
        for (int r = 0; r < 64; r++) {
            int p = bitrev6(r);
            long oi = ((bj * 64 + p) * 2 + o) * 64 + d;
            if (oi < out_cap) out2[oi] = x[r];
        }
    } else {
        float* out1 = (float*)dout;
        #pragma unroll
        for (int r = 0; r < 64; r++) {
            int p = bitrev6(r);
            long oi = ((bj * 64 + p) * 2 + o) * 64 + d;
            if (oi < out_cap) out1[oi] = x[r].x;    // real part
        }
    }
}

// ---------------------------------------------------------------------------
// Host dispatch (identical to the passing R6-R10 logic).
// ---------------------------------------------------------------------------
extern "C" void kernel_launch(void* const* d_in, const int* in_sizes, int n_in,
                              void* d_out, int out_size) {
    if (n_in < 7) return;

    const float* sph[2] = {0, 0};
    const float* ker[2] = {0, 0};
    const float* leg[2] = {0, 0};
    const float* w = 0;
    int ns = 0, nk = 0, nl = 0;

    for (int t = 0; t < n_in; t++) {
        const float* p = (const float*)d_in[t];
        int sz = in_sizes[t];
        if (sz == SZ_SPHERE && ns < 2) sph[ns++] = p;
        else if (sz == SZ_KERNEL && nk < 2) ker[nk++] = p;
        else if (sz == SZ_LEG && nl < 2) leg[nl++] = p;
        else if (sz == SZ_W && !w) w = p;
    }
    if (ns != 2 || nk != 2 || nl != 2 || !w) return;

    bool alpha = (n_in == 7 &&
                  in_sizes[0] == SZ_KERNEL && in_sizes[1] == SZ_KERNEL &&
                  in_sizes[2] == SZ_LEG    && in_sizes[3] == SZ_LEG &&
                  in_sizes[4] == SZ_W      &&
                  in_sizes[5] == SZ_SPHERE && in_sizes[6] == SZ_SPHERE);

    const float *fre, *fim, *kre, *kim;
    if (alpha) { fim = sph[0]; fre = sph[1]; kim = ker[0]; kre = ker[1]; }
    else       { fre = sph[0]; fim = sph[1]; kre = ker[0]; kim = ker[1]; }
    const float* leg_in = leg[0];
    const float* leg_out = leg[1];

    int mode;
    long cap;
    if (out_size == 33554432)      { mode = 1; cap = 16777216; }   // float2 count
    else if (out_size == 16777216) { mode = 0; cap = 16777216; }   // float count
    else                           { mode = 0; cap = (long)out_size; }

    k1_fft   <<<4096, 64>>>(fre, fim);
    k2_theta <<<dim3(63, 2, 32), 256>>>(leg_in, w);
    k3_gemm  <<<dim3(2, 32, 32), 256>>>(kre, kim);
    k4_itheta<<<dim3(63, 2, 32), 256>>>(leg_out);
    k5_ifft  <<<4096, 64>>>(d_out, mode, cap);
}

// round 12
// speedup vs baseline: 1.1856x; 1.1419x over previous
#include <cuda_runtime.h>
#include <cuda_fp16.h>

// B=32, R=64 (theta j, phi p), L=32, M=63, spins=2, C=64. All inputs f32.
#define TWO_PI_F 6.28318530717958647692f

#define SZ_SPHERE 16777216
#define SZ_KERNEL 524288
#define SZ_LEG    258048
#define SZ_W      64

// Packed (l,m): row(l,b,mm) = 32*l*l + b*(2l+1) + mm, mm = m-31+l in [0,2l].
#define N_A 4194304            // 32768*128 float2
#define N_G 16515072           // G (b,i,m,j,c) float2; H region reuses this as half2

__device__ float2 g_G   [N_G];
__device__ float2 g_Ain [N_A];
__device__ float2 g_Aout[N_A];

typedef unsigned long long ull;

__device__ __forceinline__ ull pk2(float lo, float hi) {
    ull r; asm("mov.b64 %0, {%1,%2};" : "=l"(r) : "f"(lo), "f"(hi)); return r;
}
__device__ __forceinline__ ull ffma2(ull a, ull b, ull c) {
    ull d; asm("fma.rn.f32x2 %0, %1, %2, %3;" : "=l"(d) : "l"(a), "l"(b), "l"(c)); return d;
}
__device__ __forceinline__ float2 upk2(ull v) {
    float2 f; asm("mov.b64 {%0,%1}, %2;" : "=f"(f.x), "=f"(f.y) : "l"(v)); return f;
}
__device__ __forceinline__ float2 pq(ull P, ull Q) {
    float2 p = upk2(P), q = upk2(Q);
    return make_float2(p.x - q.y, p.y + q.x);
}

// ---------------------------------------------------------------------------
// FFT-64: radix-2 DIF, natural input -> bit-reversed output.
// ---------------------------------------------------------------------------
__constant__ float cW[32] = {
    1.0f, 0.99518472667f, 0.98078528040f, 0.95694033573f,
    0.92387953251f, 0.88192126435f, 0.83146961230f, 0.77301045336f,
    0.70710678119f, 0.63439328416f, 0.55557023302f, 0.47139673683f,
    0.38268343236f, 0.29028467725f, 0.19509032202f, 0.09801714033f,
    0.0f, -0.09801714033f, -0.19509032202f, -0.29028467725f,
    -0.38268343236f, -0.47139673683f, -0.55557023302f, -0.63439328416f,
    -0.70710678119f, -0.77301045336f, -0.83146961230f, -0.88192126435f,
    -0.92387953251f, -0.95694033573f, -0.98078528040f, -0.99518472667f };
__constant__ float sW[32] = {
    0.0f, 0.09801714033f, 0.19509032202f, 0.29028467725f,
    0.38268343236f, 0.47139673683f, 0.55557023302f, 0.63439328416f,
    0.70710678119f, 0.77301045336f, 0.83146961230f, 0.88192126435f,
    0.92387953251f, 0.95694033573f, 0.98078528040f, 0.99518472667f,
    1.0f, 0.99518472667f, 0.98078528040f, 0.95694033573f,
    0.92387953251f, 0.88192126435f, 0.83146961230f, 0.77301045336f,
    0.70710678119f, 0.63439328416f, 0.55557023302f, 0.47139673683f,
    0.38268343236f, 0.29028467725f, 0.19509032202f, 0.09801714033f };

__device__ __forceinline__ constexpr int bitrev6(int i) {
    return ((i & 1) << 5) | ((i & 2) << 3) | ((i & 4) << 1)
         | ((i & 8) >> 1) | ((i & 16) >> 3) | ((i & 32) >> 5);
}

template <int LEN, bool INV>
__device__ __forceinline__ void fft_stage(float2* x) {
    constexpr int HALF = LEN / 2;
    constexpr int STEP = 64 / LEN;
    #pragma unroll
    for (int st = 0; st < 64; st += LEN) {
        #pragma unroll
        for (int k = 0; k < HALF; k++) {
            float2 u = x[st + k], v = x[st + k + HALF];
            x[st + k] = make_float2(u.x + v.x, u.y + v.y);
            float2 t = make_float2(u.x - v.x, u.y - v.y);
            if (k == 0) {
                x[st + k + HALF] = t;
            } else {
                float wr = cW[k * STEP];
                float wi = INV ? sW[k * STEP] : -sW[k * STEP];
                x[st + k + HALF] = make_float2(t.x * wr - t.y * wi,
                                               t.x * wi + t.y * wr);
            }
        }
    }
}

template <bool INV>
__device__ __forceinline__ void fft64(float2* x) {
    fft_stage<64, INV>(x);
    fft_stage<32, INV>(x);
    fft_stage<16, INV>(x);
    fft_stage<8,  INV>(x);
    fft_stage<4,  INV>(x);
    fft_stage<2,  INV>(x);
}

// ---------------------------------------------------------------------------
// k1: forward FFT over phi. G[b,i,m,j,c] = X[(m-31)&63]/64, X = fft_p(f).
// ---------------------------------------------------------------------------
__global__ void k1_fft(const float* __restrict__ fre, const float* __restrict__ fim) {
    int bid = blockIdx.x;
    int j = bid & 63, bi = bid >> 6;
    int i = bi & 1,  b = bi >> 1;
    int c = threadIdx.x;   // 0..63

    long base = (long)(b * 64 + j) * 8192 + i * 64 + c;   // + p*128
    float2 x[64];
    #pragma unroll
    for (int p = 0; p < 64; p++) {
        long a = base + (long)p * 128;
        x[p] = make_float2(fre[a] * (1.0f / 64.0f), fim[a] * (1.0f / 64.0f));
    }
    fft64<false>(x);

    long gb = (long)bi * 63 * 4096 + (long)j * 64 + c;
    #pragma unroll
    for (int r = 0; r < 64; r++) {
        int k = bitrev6(r);
        if (k != 32) {                       // m==63 bin doesn't exist
            int m = (k + 31) & 63;
            g_G[gb + (long)m * 4096] = x[r];
        }
    }
}

// ---------------------------------------------------------------------------
// k2: theta quadrature, packed output (R9 exact — occupancy-optimal).
// A_in[row(l,b,mm), i*64+c] = sum_j (2pi w_j leg_in[i,l,m,j]) G[b,i,m,j,c]
// ---------------------------------------------------------------------------
__global__ void k2_theta(const float* __restrict__ leg_in, const float* __restrict__ w) {
    __shared__ float2 sh_g[64][64];   // [j][c]
    __shared__ float  sh_P[32][64];   // [l][j]

    int m = blockIdx.x, i = blockIdx.y, b = blockIdx.z;
    int tid = threadIdx.x;
    int bi = b * 2 + i;

    long gbase = ((long)bi * 63 + m) * 4096;
    for (int e = tid; e < 4096; e += 256) sh_g[e >> 6][e & 63] = g_G[gbase + e];
    for (int e = tid; e < 2048; e += 256) {
        int l = e >> 6, jj = e & 63;
        sh_P[l][jj] = TWO_PI_F * w[jj] * leg_in[((i * 32 + l) * 63 + m) * 64 + jj];
    }
    __syncthreads();

    int c = tid & 63, lq = tid >> 6;
    int lmin = (m <= 31) ? (31 - m) : (m - 31);
    int nv = 32 - lmin;
    float2 acc[8];
    #pragma unroll
    for (int u = 0; u < 8; u++) acc[u] = make_float2(0.0f, 0.0f);

    for (int jj = 0; jj < 64; jj++) {
        float2 g = sh_g[jj][c];
        #pragma unroll
        for (int u = 0; u < 8; u++) {
            int l = lmin + lq + 4 * u;
            float pl = (l < 32) ? sh_P[l][jj] : 0.0f;
            acc[u].x += pl * g.x;
            acc[u].y += pl * g.y;
        }
    }
    #pragma unroll
    for (int u = 0; u < 8; u++) {
        int lv = lq + 4 * u;
        if (lv < nv) {
            int l = lmin + lv;
            int mm = (m - 31) + l;
            long row = (long)(32 * l * l) + b * (2 * l + 1) + mm;
            g_Ain[row * 128 + i * 64 + c] = acc[u];
        }
    }
}

// ---------------------------------------------------------------------------
// k3: per-l complex GEMM on packed rows, P/Q split (unchanged — passing).
// ---------------------------------------------------------------------------
__global__ void k3_gemm(const float* __restrict__ kre, const float* __restrict__ kim) {
    __shared__ float2     sA[16][64];
    __shared__ ulonglong2 sB[16][64];

    int o = blockIdx.x, rt = blockIdx.y, l = blockIdx.z;
    int nrow = 32 * (2 * l + 1);
    int row0 = rt * 64;
    if (row0 >= nrow) return;

    int tid = threadIdx.x, tx = tid & 15, ty = tid >> 4;
    ull accP[4][4], accQ[4][4];
    #pragma unroll
    for (int ri = 0; ri < 4; ri++)
        #pragma unroll
        for (int ci = 0; ci < 4; ci++) { accP[ri][ci] = 0ull; accQ[ri][ci] = 0ull; }

    long Abase = (long)(32 * l * l) * 128;
    long wbase = (long)l * 16384 + (long)o * 4096;

    for (int k0 = 0; k0 < 128; k0 += 16) {
        #pragma unroll
        for (int t = 0; t < 4; t++) {
            int e = tid + t * 256;
            int rr = e >> 4, kk = e & 15;
            int grow = row0 + rr;
            float2 v = make_float2(0.0f, 0.0f);
            if (grow < nrow) v = g_Ain[Abase + (long)grow * 128 + k0 + kk];
            sA[kk][rr] = v;
        }
        #pragma unroll
        for (int t = 0; t < 4; t++) {
            int e = tid + t * 256;
            int kk = e >> 6, col = e & 63;
            int ic = k0 + kk;
            long a = wbase + (long)(ic >> 6) * 8192 + (ic & 63) * 64 + col;
            float br = kre[a], bim = kim[a];
            sB[kk][col] = make_ulonglong2(pk2(br, br), pk2(bim, bim));
        }
        __syncthreads();
        #pragma unroll
        for (int kk = 0; kk < 16; kk++) {
            ull av[4];
            ulonglong2 bq[4];
            #pragma unroll
            for (int u = 0; u < 4; u++) av[u] = *(const ull*)&sA[kk][ty + 16 * u];
            #pragma unroll
            for (int u = 0; u < 4; u++) bq[u] = sB[kk][tx + 16 * u];
            #pragma unroll
            for (int ri = 0; ri < 4; ri++)
                #pragma unroll
                for (int ci = 0; ci < 4; ci++) {
                    accP[ri][ci] = ffma2(bq[ci].x, av[ri], accP[ri][ci]);
                    accQ[ri][ci] = ffma2(bq[ci].y, av[ri], accQ[ri][ci]);
                }
        }
        __syncthreads();
    }
    #pragma unroll
    for (int ri = 0; ri < 4; ri++) {
        int grow = row0 + ty + 16 * ri;
        if (grow < nrow) {
            #pragma unroll
            for (int ci = 0; ci < 4; ci++)
                g_Aout[Abase + (long)grow * 128 + o * 64 + tx + 16 * ci] =
                    pq(accP[ri][ci], accQ[ri][ci]);
        }
    }
}

// ---------------------------------------------------------------------------
// k4: inverse theta (R9 exact shapes) — only the H store becomes half2.
// H[b,j,o,m,d] = sum_{l>=lmin} leg_out[o,l,m,j] * A_out[row(l,b,m-31+l), o*64+d]
// ---------------------------------------------------------------------------
__global__ void k4_itheta(const float* __restrict__ leg_out) {
    __shared__ float2 sh_a[32][64];   // [l][d]
    __shared__ ull    sh_Q[32][64];   // [l][j] dup (q,q)

    int m = blockIdx.x, o = blockIdx.y, b = blockIdx.z;
    int tid = threadIdx.x;
    int lmin = (m <= 31) ? (31 - m) : (m - 31);

    for (int e = tid; e < 2048; e += 256) {
        int l = e >> 6, d = e & 63;
        float2 v = make_float2(0.0f, 0.0f);
        if (l >= lmin) {
            int mm = m - 31 + l;
            long row = (long)(32 * l * l) + b * (2 * l + 1) + mm;
            v = g_Aout[row * 128 + o * 64 + d];
        }
        sh_a[l][d] = v;
    }
    for (int e = tid; e < 2048; e += 256) {
        int l = e >> 6, j = e & 63;
        float q = leg_out[((o * 32 + l) * 63 + m) * 64 + j];
        sh_Q[l][j] = pk2(q, q);
    }
    __syncthreads();

    int d = tid & 63, jq = tid >> 6;
    ull acc[16];
    #pragma unroll
    for (int u = 0; u < 16; u++) acc[u] = 0ull;

    for (int l = lmin; l < 32; l++) {
        ull a = *(const ull*)&sh_a[l][d];
        #pragma unroll
        for (int u = 0; u < 16; u++)
            acc[u] = ffma2(sh_Q[l][jq + 4 * u], a, acc[u]);
    }
    __half2* gH = (__half2*)g_G;      // H region (fp16 complex), G is dead now
    #pragma unroll
    for (int u = 0; u < 16; u++) {
        int j = jq + 4 * u;
        float2 r = upk2(acc[u]);
        gH[(long)((b * 64 + j) * 2 + o) * 4032 + m * 64 + d] =
            __floats2half2_rn(r.x, r.y);
    }
}

// ---------------------------------------------------------------------------
// k5: inverse FFT over phi, H read as half2. X[(m-31)&63]=H[m], X[32]=0.
// ---------------------------------------------------------------------------
__global__ void k5_ifft(void* __restrict__ dout, int mode, long out_cap) {
    int bid = blockIdx.x;             // matches k4's H layout
    int d = threadIdx.x;              // 0..63

    const __half2* gH = (const __half2*)g_G;
    long hb = (long)bid * 4032 + d;
    float2 x[64];
    #pragma unroll
    for (int k = 0; k < 64; k++) {
        if (k == 32) x[k] = make_float2(0.0f, 0.0f);
        else {
            int m = (k + 31) & 63;
            x[k] = __half22float2(gH[hb + (long)m * 64]);
        }
    }
    fft64<true>(x);

    int o = bid & 1;
    long bj = (long)(bid >> 1);
    if (mode == 1) {
        float2* out2 = (float2*)dout;
        #pragma unroll
        for (int r = 0; r < 64; r++) {
            int p = bitrev6(r);
            long oi = ((bj * 64 + p) * 2 + o) * 64 + d;
            if (oi < out_cap) out2[oi] = x[r];
        }
    } else {
        float* out1 = (float*)dout;
        #pragma unroll
        for (int r = 0; r < 64; r++) {
            int p = bitrev6(r);
            long oi = ((bj * 64 + p) * 2 + o) * 64 + d;
            if (oi < out_cap) out1[oi] = x[r].x;    // real part
        }
    }
}

// ---------------------------------------------------------------------------
// Host dispatch (identical to the passing R6-R11 logic).
// ---------------------------------------------------------------------------
extern "C" void kernel_launch(void* const* d_in, const int* in_sizes, int n_in,
                              void* d_out, int out_size) {
    if (n_in < 7) return;

    const float* sph[2] = {0, 0};
    const float* ker[2] = {0, 0};
    const float* leg[2] = {0, 0};
    const float* w = 0;
    int ns = 0, nk = 0, nl = 0;

    for (int t = 0; t < n_in; t++) {
        const float* p = (const float*)d_in[t];
        int sz = in_sizes[t];
        if (sz == SZ_SPHERE && ns < 2) sph[ns++] = p;
        else if (sz == SZ_KERNEL && nk < 2) ker[nk++] = p;
        else if (sz == SZ_LEG && nl < 2) leg[nl++] = p;
        else if (sz == SZ_W && !w) w = p;
    }
    if (ns != 2 || nk != 2 || nl != 2 || !w) return;

    bool alpha = (n_in == 7 &&
                  in_sizes[0] == SZ_KERNEL && in_sizes[1] == SZ_KERNEL &&
                  in_sizes[2] == SZ_LEG    && in_sizes[3] == SZ_LEG &&
                  in_sizes[4] == SZ_W      &&
                  in_sizes[5] == SZ_SPHERE && in_sizes[6] == SZ_SPHERE);

    const float *fre, *fim, *kre, *kim;
    if (alpha) { fim = sph[0]; fre = sph[1]; kim = ker[0]; kre = ker[1]; }
    else       { fre = sph[0]; fim = sph[1]; kre = ker[0]; kim = ker[1]; }
    const float* leg_in = leg[0];
    const float* leg_out = leg[1];

    int mode;
    long cap;
    if (out_size == 33554432)      { mode = 1; cap = 16777216; }   // float2 count
    else if (out_size == 16777216) { mode = 0; cap = 16777216; }   // float count
    else                           { mode = 0; cap = (long)out_size; }

    k1_fft   <<<4096, 64>>>(fre, fim);
    k2_theta <<<dim3(63, 2, 32), 256>>>(leg_in, w);
    k3_gemm  <<<dim3(2, 32, 32), 256>>>(kre, kim);
    k4_itheta<<<dim3(63, 2, 32), 256>>>(leg_out);
    k5_ifft  <<<4096, 64>>>(d_out, mode, cap);
}

// round 13
// speedup vs baseline: 1.2055x; 1.0168x over previous
#include <cuda_runtime.h>
#include <cuda_fp16.h>

// B=32, R=64 (theta j, phi p), L=32, M=63, spins=2, C=64. All inputs f32.
#define TWO_PI_F 6.28318530717958647692f

#define SZ_SPHERE 16777216
#define SZ_KERNEL 524288
#define SZ_LEG    258048
#define SZ_W      64

// Packed (l,m): row(l,b,mm) = 32*l*l + b*(2l+1) + mm, mm = m-31+l in [0,2l].
#define N_A 4194304            // 32768*128 float2
#define N_G 16515072           // region sized in float2; G and H live here as half2

__device__ float2 g_G   [N_G];  // used as __half2[] for both G and H phases
__device__ float2 g_Ain [N_A];
__device__ float2 g_Aout[N_A];

typedef unsigned long long ull;

__device__ __forceinline__ ull pk2(float lo, float hi) {
    ull r; asm("mov.b64 %0, {%1,%2};" : "=l"(r) : "f"(lo), "f"(hi)); return r;
}
__device__ __forceinline__ ull ffma2(ull a, ull b, ull c) {
    ull d; asm("fma.rn.f32x2 %0, %1, %2, %3;" : "=l"(d) : "l"(a), "l"(b), "l"(c)); return d;
}
__device__ __forceinline__ float2 upk2(ull v) {
    float2 f; asm("mov.b64 {%0,%1}, %2;" : "=f"(f.x), "=f"(f.y) : "l"(v)); return f;
}
__device__ __forceinline__ float2 pq(ull P, ull Q) {
    float2 p = upk2(P), q = upk2(Q);
    return make_float2(p.x - q.y, p.y + q.x);
}

// ---------------------------------------------------------------------------
// FFT-64: radix-2 DIF, natural input -> bit-reversed output.
// ---------------------------------------------------------------------------
__constant__ float cW[32] = {
    1.0f, 0.99518472667f, 0.98078528040f, 0.95694033573f,
    0.92387953251f, 0.88192126435f, 0.83146961230f, 0.77301045336f,
    0.70710678119f, 0.63439328416f, 0.55557023302f, 0.47139673683f,
    0.38268343236f, 0.29028467725f, 0.19509032202f, 0.09801714033f,
    0.0f, -0.09801714033f, -0.19509032202f, -0.29028467725f,
    -0.38268343236f, -0.47139673683f, -0.55557023302f, -0.63439328416f,
    -0.70710678119f, -0.77301045336f, -0.83146961230f, -0.88192126435f,
    -0.92387953251f, -0.95694033573f, -0.98078528040f, -0.99518472667f };
__constant__ float sW[32] = {
    0.0f, 0.09801714033f, 0.19509032202f, 0.29028467725f,
    0.38268343236f, 0.47139673683f, 0.55557023302f, 0.63439328416f,
    0.70710678119f, 0.77301045336f, 0.83146961230f, 0.88192126435f,
    0.92387953251f, 0.95694033573f, 0.98078528040f, 0.99518472667f,
    1.0f, 0.99518472667f, 0.98078528040f, 0.95694033573f,
    0.92387953251f, 0.88192126435f, 0.83146961230f, 0.77301045336f,
    0.70710678119f, 0.63439328416f, 0.55557023302f, 0.47139673683f,
    0.38268343236f, 0.29028467725f, 0.19509032202f, 0.09801714033f };

__device__ __forceinline__ constexpr int bitrev6(int i) {
    return ((i & 1) << 5) | ((i & 2) << 3) | ((i & 4) << 1)
         | ((i & 8) >> 1) | ((i & 16) >> 3) | ((i & 32) >> 5);
}

template <int LEN, bool INV>
__device__ __forceinline__ void fft_stage(float2* x) {
    constexpr int HALF = LEN / 2;
    constexpr int STEP = 64 / LEN;
    #pragma unroll
    for (int st = 0; st < 64; st += LEN) {
        #pragma unroll
        for (int k = 0; k < HALF; k++) {
            float2 u = x[st + k], v = x[st + k + HALF];
            x[st + k] = make_float2(u.x + v.x, u.y + v.y);
            float2 t = make_float2(u.x - v.x, u.y - v.y);
            if (k == 0) {
                x[st + k + HALF] = t;
            } else {
                float wr = cW[k * STEP];
                float wi = INV ? sW[k * STEP] : -sW[k * STEP];
                x[st + k + HALF] = make_float2(t.x * wr - t.y * wi,
                                               t.x * wi + t.y * wr);
            }
        }
    }
}

template <bool INV>
__device__ __forceinline__ void fft64(float2* x) {
    fft_stage<64, INV>(x);
    fft_stage<32, INV>(x);
    fft_stage<16, INV>(x);
    fft_stage<8,  INV>(x);
    fft_stage<4,  INV>(x);
    fft_stage<2,  INV>(x);
}

// ---------------------------------------------------------------------------
// k1: forward FFT over phi. G[b,i,m,j,c] = X[(m-31)&63]/64, X = fft_p(f).
// G stored as half2 (fp16 complex).
// ---------------------------------------------------------------------------
__global__ void k1_fft(const float* __restrict__ fre, const float* __restrict__ fim) {
    int bid = blockIdx.x;
    int j = bid & 63, bi = bid >> 6;
    int i = bi & 1,  b = bi >> 1;
    int c = threadIdx.x;   // 0..63

    long base = (long)(b * 64 + j) * 8192 + i * 64 + c;   // + p*128
    float2 x[64];
    #pragma unroll
    for (int p = 0; p < 64; p++) {
        long a = base + (long)p * 128;
        x[p] = make_float2(fre[a] * (1.0f / 64.0f), fim[a] * (1.0f / 64.0f));
    }
    fft64<false>(x);

    __half2* gG = (__half2*)g_G;
    long gb = (long)bi * 63 * 4096 + (long)j * 64 + c;
    #pragma unroll
    for (int r = 0; r < 64; r++) {
        int k = bitrev6(r);
        if (k != 32) {                       // m==63 bin doesn't exist
            int m = (k + 31) & 63;
            gG[gb + (long)m * 4096] = __floats2half2_rn(x[r].x, x[r].y);
        }
    }
}

// ---------------------------------------------------------------------------
// k2: theta quadrature, packed output (R9 shapes; G read as half2).
// A_in[row(l,b,mm), i*64+c] = sum_j (2pi w_j leg_in[i,l,m,j]) G[b,i,m,j,c]
// ---------------------------------------------------------------------------
__global__ void k2_theta(const float* __restrict__ leg_in, const float* __restrict__ w) {
    __shared__ float2 sh_g[64][64];   // [j][c]
    __shared__ float  sh_P[32][64];   // [l][j]

    int m = blockIdx.x, i = blockIdx.y, b = blockIdx.z;
    int tid = threadIdx.x;
    int bi = b * 2 + i;

    const __half2* gG = (const __half2*)g_G;
    long gbase = ((long)bi * 63 + m) * 4096;
    for (int e = tid; e < 4096; e += 256)
        sh_g[e >> 6][e & 63] = __half22float2(gG[gbase + e]);
    for (int e = tid; e < 2048; e += 256) {
        int l = e >> 6, jj = e & 63;
        sh_P[l][jj] = TWO_PI_F * w[jj] * leg_in[((i * 32 + l) * 63 + m) * 64 + jj];
    }
    __syncthreads();

    int c = tid & 63, lq = tid >> 6;
    int lmin = (m <= 31) ? (31 - m) : (m - 31);
    int nv = 32 - lmin;
    float2 acc[8];
    #pragma unroll
    for (int u = 0; u < 8; u++) acc[u] = make_float2(0.0f, 0.0f);

    for (int jj = 0; jj < 64; jj++) {
        float2 g = sh_g[jj][c];
        #pragma unroll
        for (int u = 0; u < 8; u++) {
            int l = lmin + lq + 4 * u;
            float pl = (l < 32) ? sh_P[l][jj] : 0.0f;
            acc[u].x += pl * g.x;
            acc[u].y += pl * g.y;
        }
    }
    #pragma unroll
    for (int u = 0; u < 8; u++) {
        int lv = lq + 4 * u;
        if (lv < nv) {
            int l = lmin + lv;
            int mm = (m - 31) + l;
            long row = (long)(32 * l * l) + b * (2 * l + 1) + mm;
            g_Ain[row * 128 + i * 64 + c] = acc[u];
        }
    }
}

// ---------------------------------------------------------------------------
// k3: per-l complex GEMM on packed rows, P/Q split (unchanged — passing).
// ---------------------------------------------------------------------------
__global__ void k3_gemm(const float* __restrict__ kre, const float* __restrict__ kim) {
    __shared__ float2     sA[16][64];
    __shared__ ulonglong2 sB[16][64];

    int o = blockIdx.x, rt = blockIdx.y, l = blockIdx.z;
    int nrow = 32 * (2 * l + 1);
    int row0 = rt * 64;
    if (row0 >= nrow) return;

    int tid = threadIdx.x, tx = tid & 15, ty = tid >> 4;
    ull accP[4][4], accQ[4][4];
    #pragma unroll
    for (int ri = 0; ri < 4; ri++)
        #pragma unroll
        for (int ci = 0; ci < 4; ci++) { accP[ri][ci] = 0ull; accQ[ri][ci] = 0ull; }

    long Abase = (long)(32 * l * l) * 128;
    long wbase = (long)l * 16384 + (long)o * 4096;

    for (int k0 = 0; k0 < 128; k0 += 16) {
        #pragma unroll
        for (int t = 0; t < 4; t++) {
            int e = tid + t * 256;
            int rr = e >> 4, kk = e & 15;
            int grow = row0 + rr;
            float2 v = make_float2(0.0f, 0.0f);
            if (grow < nrow) v = g_Ain[Abase + (long)grow * 128 + k0 + kk];
            sA[kk][rr] = v;
        }
        #pragma unroll
        for (int t = 0; t < 4; t++) {
            int e = tid + t * 256;
            int kk = e >> 6, col = e & 63;
            int ic = k0 + kk;
            long a = wbase + (long)(ic >> 6) * 8192 + (ic & 63) * 64 + col;
            float br = kre[a], bim = kim[a];
            sB[kk][col] = make_ulonglong2(pk2(br, br), pk2(bim, bim));
        }
        __syncthreads();
        #pragma unroll
        for (int kk = 0; kk < 16; kk++) {
            ull av[4];
            ulonglong2 bq[4];
            #pragma unroll
            for (int u = 0; u < 4; u++) av[u] = *(const ull*)&sA[kk][ty + 16 * u];
            #pragma unroll
            for (int u = 0; u < 4; u++) bq[u] = sB[kk][tx + 16 * u];
            #pragma unroll
            for (int ri = 0; ri < 4; ri++)
                #pragma unroll
                for (int ci = 0; ci < 4; ci++) {
                    accP[ri][ci] = ffma2(bq[ci].x, av[ri], accP[ri][ci]);
                    accQ[ri][ci] = ffma2(bq[ci].y, av[ri], accQ[ri][ci]);
                }
        }
        __syncthreads();
    }
    #pragma unroll
    for (int ri = 0; ri < 4; ri++) {
        int grow = row0 + ty + 16 * ri;
        if (grow < nrow) {
            #pragma unroll
            for (int ci = 0; ci < 4; ci++)
                g_Aout[Abase + (long)grow * 128 + o * 64 + tx + 16 * ci] =
                    pq(accP[ri][ci], accQ[ri][ci]);
        }
    }
}

// ---------------------------------------------------------------------------
// k4: inverse theta (R9 shapes, fp16 H store). launch_bounds forces <=51 regs
// to keep 5 resident blocks (52 regs in R12 dropped occupancy 57.6->46.1%).
// H[b,j,o,m,d] = sum_{l>=lmin} leg_out[o,l,m,j] * A_out[row(l,b,m-31+l), o*64+d]
// ---------------------------------------------------------------------------
__global__ void __launch_bounds__(256, 5)
k4_itheta(const float* __restrict__ leg_out) {
    __shared__ float2 sh_a[32][64];   // [l][d]
    __shared__ ull    sh_Q[32][64];   // [l][j] dup (q,q)

    int m = blockIdx.x, o = blockIdx.y, b = blockIdx.z;
    int tid = threadIdx.x;
    int lmin = (m <= 31) ? (31 - m) : (m - 31);

    for (int e = tid; e < 2048; e += 256) {
        int l = e >> 6, d = e & 63;
        float2 v = make_float2(0.0f, 0.0f);
        if (l >= lmin) {
            int mm = m - 31 + l;
            long row = (long)(32 * l * l) + b * (2 * l + 1) + mm;
            v = g_Aout[row * 128 + o * 64 + d];
        }
        sh_a[l][d] = v;
    }
    for (int e = tid; e < 2048; e += 256) {
        int l = e >> 6, j = e & 63;
        float q = leg_out[((o * 32 + l) * 63 + m) * 64 + j];
        sh_Q[l][j] = pk2(q, q);
    }
    __syncthreads();

    int d = tid & 63, jq = tid >> 6;
    ull acc[16];
    #pragma unroll
    for (int u = 0; u < 16; u++) acc[u] = 0ull;

    for (int l = lmin; l < 32; l++) {
        ull a = *(const ull*)&sh_a[l][d];
        #pragma unroll
        for (int u = 0; u < 16; u++)
            acc[u] = ffma2(sh_Q[l][jq + 4 * u], a, acc[u]);
    }
    __half2* gH = (__half2*)g_G;      // H region (fp16 complex), G is dead now
    #pragma unroll
    for (int u = 0; u < 16; u++) {
        int j = jq + 4 * u;
        float2 r = upk2(acc[u]);
        gH[(long)((b * 64 + j) * 2 + o) * 4032 + m * 64 + d] =
            __floats2half2_rn(r.x, r.y);
    }
}

// ---------------------------------------------------------------------------
// k5: inverse FFT over phi, H read as half2. X[(m-31)&63]=H[m], X[32]=0.
// ---------------------------------------------------------------------------
__global__ void k5_ifft(void* __restrict__ dout, int mode, long out_cap) {
    int bid = blockIdx.x;             // matches k4's H layout
    int d = threadIdx.x;              // 0..63

    const __half2* gH = (const __half2*)g_G;
    long hb = (long)bid * 4032 + d;
    float2 x[64];
    #pragma unroll
    for (int k = 0; k < 64; k++) {
        if (k == 32) x[k] = make_float2(0.0f, 0.0f);
        else {
            int m = (k + 31) & 63;
            x[k] = __half22float2(gH[hb + (long)m * 64]);
        }
    }
    fft64<true>(x);

    int o = bid & 1;
    long bj = (long)(bid >> 1);
    if (mode == 1) {
        float2* out2 = (float2*)dout;
        #pragma unroll
        for (int r = 0; r < 64; r++) {
            int p = bitrev6(r);
            long oi = ((bj * 64 + p) * 2 + o) * 64 + d;
            if (oi < out_cap) out2[oi] = x[r];
        }
    } else {
        float* out1 = (float*)dout;
        #pragma unroll
        for (int r = 0; r < 64; r++) {
            int p = bitrev6(r);
            long oi = ((bj * 64 + p) * 2 + o) * 64 + d;
            if (oi < out_cap) out1[oi] = x[r].x;    // real part
        }
    }
}

// ---------------------------------------------------------------------------
// Host dispatch (identical to the passing R6-R12 logic).
// ---------------------------------------------------------------------------
extern "C" void kernel_launch(void* const* d_in, const int* in_sizes, int n_in,
                              void* d_out, int out_size) {
    if (n_in < 7) return;

    const float* sph[2] = {0, 0};
    const float* ker[2] = {0, 0};
    const float* leg[2] = {0, 0};
    const float* w = 0;
    int ns = 0, nk = 0, nl = 0;

    for (int t = 0; t < n_in; t++) {
        const float* p = (const float*)d_in[t];
        int sz = in_sizes[t];
        if (sz == SZ_SPHERE && ns < 2) sph[ns++] = p;
        else if (sz == SZ_KERNEL && nk < 2) ker[nk++] = p;
        else if (sz == SZ_LEG && nl < 2) leg[nl++] = p;
        else if (sz == SZ_W && !w) w = p;
    }
    if (ns != 2 || nk != 2 || nl != 2 || !w) return;

    bool alpha = (n_in == 7 &&
                  in_sizes[0] == SZ_KERNEL && in_sizes[1] == SZ_KERNEL &&
                  in_sizes[2] == SZ_LEG    && in_sizes[3] == SZ_LEG &&
                  in_sizes[4] == SZ_W      &&
                  in_sizes[5] == SZ_SPHERE && in_sizes[6] == SZ_SPHERE);

    const float *fre, *fim, *kre, *kim;
    if (alpha) { fim = sph[0]; fre = sph[1]; kim = ker[0]; kre = ker[1]; }
    else       { fre = sph[0]; fim = sph[1]; kre = ker[0]; kim = ker[1]; }
    const float* leg_in = leg[0];
    const float* leg_out = leg[1];

    int mode;
    long cap;
    if (out_size == 33554432)      { mode = 1; cap = 16777216; }   // float2 count
    else if (out_size == 16777216) { mode = 0; cap = 16777216; }   // float count
    else                           { mode = 0; cap = (long)out_size; }

    k1_fft   <<<4096, 64>>>(fre, fim);
    k2_theta <<<dim3(63, 2, 32), 256>>>(leg_in, w);
    k3_gemm  <<<dim3(2, 32, 32), 256>>>(kre, kim);
    k4_itheta<<<dim3(63, 2, 32), 256>>>(leg_out);
    k5_ifft  <<<4096, 64>>>(d_out, mode, cap);
}

// round 14
// speedup vs baseline: 1.2182x; 1.0105x over previous
#include <cuda_runtime.h>
#include <cuda_fp16.h>

// B=32, R=64 (theta j, phi p), L=32, M=63, spins=2, C=64. All inputs f32.
#define TWO_PI_F 6.28318530717958647692f

#define SZ_SPHERE 16777216
#define SZ_KERNEL 524288
#define SZ_LEG    258048
#define SZ_W      64

// Packed (l,m): row(l,b,mm) = 32*l*l + b*(2l+1) + mm, mm = m-31+l in [0,2l].
#define N_A 4194304            // 32768*128 float2
#define N_G 16515072           // region sized in float2; G and H live here as half2

__device__ float2 g_G   [N_G];  // used as __half2[] for both G and H phases
__device__ float2 g_Ain [N_A];
__device__ float2 g_Aout[N_A];

typedef unsigned long long ull;

__device__ __forceinline__ ull pk2(float lo, float hi) {
    ull r; asm("mov.b64 %0, {%1,%2};" : "=l"(r) : "f"(lo), "f"(hi)); return r;
}
__device__ __forceinline__ ull ffma2(ull a, ull b, ull c) {
    ull d; asm("fma.rn.f32x2 %0, %1, %2, %3;" : "=l"(d) : "l"(a), "l"(b), "l"(c)); return d;
}
__device__ __forceinline__ float2 upk2(ull v) {
    float2 f; asm("mov.b64 {%0,%1}, %2;" : "=f"(f.x), "=f"(f.y) : "l"(v)); return f;
}
__device__ __forceinline__ float2 pq(ull P, ull Q) {
    float2 p = upk2(P), q = upk2(Q);
    return make_float2(p.x - q.y, p.y + q.x);
}

// ---------------------------------------------------------------------------
// FFT-64: radix-2 DIF, natural input -> bit-reversed output.
// ---------------------------------------------------------------------------
__constant__ float cW[32] = {
    1.0f, 0.99518472667f, 0.98078528040f, 0.95694033573f,
    0.92387953251f, 0.88192126435f, 0.83146961230f, 0.77301045336f,
    0.70710678119f, 0.63439328416f, 0.55557023302f, 0.47139673683f,
    0.38268343236f, 0.29028467725f, 0.19509032202f, 0.09801714033f,
    0.0f, -0.09801714033f, -0.19509032202f, -0.29028467725f,
    -0.38268343236f, -0.47139673683f, -0.55557023302f, -0.63439328416f,
    -0.70710678119f, -0.77301045336f, -0.83146961230f, -0.88192126435f,
    -0.92387953251f, -0.95694033573f, -0.98078528040f, -0.99518472667f };
__constant__ float sW[32] = {
    0.0f, 0.09801714033f, 0.19509032202f, 0.29028467725f,
    0.38268343236f, 0.47139673683f, 0.55557023302f, 0.63439328416f,
    0.70710678119f, 0.77301045336f, 0.83146961230f, 0.88192126435f,
    0.92387953251f, 0.95694033573f, 0.98078528040f, 0.99518472667f,
    1.0f, 0.99518472667f, 0.98078528040f, 0.95694033573f,
    0.92387953251f, 0.88192126435f, 0.83146961230f, 0.77301045336f,
    0.70710678119f, 0.63439328416f, 0.55557023302f, 0.47139673683f,
    0.38268343236f, 0.29028467725f, 0.19509032202f, 0.09801714033f };

__device__ __forceinline__ constexpr int bitrev6(int i) {
    return ((i & 1) << 5) | ((i & 2) << 3) | ((i & 4) << 1)
         | ((i & 8) >> 1) | ((i & 16) >> 3) | ((i & 32) >> 5);
}

template <int LEN, bool INV>
__device__ __forceinline__ void fft_stage(float2* x) {
    constexpr int HALF = LEN / 2;
    constexpr int STEP = 64 / LEN;
    #pragma unroll
    for (int st = 0; st < 64; st += LEN) {
        #pragma unroll
        for (int k = 0; k < HALF; k++) {
            float2 u = x[st + k], v = x[st + k + HALF];
            x[st + k] = make_float2(u.x + v.x, u.y + v.y);
            float2 t = make_float2(u.x - v.x, u.y - v.y);
            if (k == 0) {
                x[st + k + HALF] = t;
            } else {
                float wr = cW[k * STEP];
                float wi = INV ? sW[k * STEP] : -sW[k * STEP];
                x[st + k + HALF] = make_float2(t.x * wr - t.y * wi,
                                               t.x * wi + t.y * wr);
            }
        }
    }
}

template <bool INV>
__device__ __forceinline__ void fft64(float2* x) {
    fft_stage<64, INV>(x);
    fft_stage<32, INV>(x);
    fft_stage<16, INV>(x);
    fft_stage<8,  INV>(x);
    fft_stage<4,  INV>(x);
    fft_stage<2,  INV>(x);
}

// ---------------------------------------------------------------------------
// k1: forward FFT over phi. G[b,i,m,j,c] = X[(m-31)&63]/64, X = fft_p(f).
// G stored as half2 (fp16 complex).
// ---------------------------------------------------------------------------
__global__ void k1_fft(const float* __restrict__ fre, const float* __restrict__ fim) {
    int bid = blockIdx.x;
    int j = bid & 63, bi = bid >> 6;
    int i = bi & 1,  b = bi >> 1;
    int c = threadIdx.x;   // 0..63

    long base = (long)(b * 64 + j) * 8192 + i * 64 + c;   // + p*128
    float2 x[64];
    #pragma unroll
    for (int p = 0; p < 64; p++) {
        long a = base + (long)p * 128;
        x[p] = make_float2(fre[a] * (1.0f / 64.0f), fim[a] * (1.0f / 64.0f));
    }
    fft64<false>(x);

    __half2* gG = (__half2*)g_G;
    long gb = (long)bi * 63 * 4096 + (long)j * 64 + c;
    #pragma unroll
    for (int r = 0; r < 64; r++) {
        int k = bitrev6(r);
        if (k != 32) {                       // m==63 bin doesn't exist
            int m = (k + 31) & 63;
            gG[gb + (long)m * 4096] = __floats2half2_rn(x[r].x, x[r].y);
        }
    }
}

// ---------------------------------------------------------------------------
// k2: theta quadrature, packed output. Thread owns 2 adjacent c x 4 strided l;
// FFMA2 with register-duplicated P. smem stays 40 KB (5 resident blocks).
// A_in[row(l,b,mm), i*64+c] = sum_j (2pi w_j leg_in[i,l,m,j]) G[b,i,m,j,c]
// ---------------------------------------------------------------------------
__global__ void k2_theta(const float* __restrict__ leg_in, const float* __restrict__ w) {
    __shared__ float2 sh_g[64][64];   // [j][c]  32 KB
    __shared__ float  sh_P[32][64];   // [l][j]   8 KB

    int m = blockIdx.x, i = blockIdx.y, b = blockIdx.z;
    int tid = threadIdx.x;
    int bi = b * 2 + i;

    const __half2* gG = (const __half2*)g_G;
    long gbase = ((long)bi * 63 + m) * 4096;
    for (int e = tid; e < 4096; e += 256)
        sh_g[e >> 6][e & 63] = __half22float2(gG[gbase + e]);
    for (int e = tid; e < 2048; e += 256) {
        int l = e >> 6, jj = e & 63;
        sh_P[l][jj] = TWO_PI_F * w[jj] * leg_in[((i * 32 + l) * 63 + m) * 64 + jj];
    }
    __syncthreads();

    int dq = tid & 31, lq = tid >> 5;   // c pair = {2dq, 2dq+1}; l = lmin+lq+8u
    int c2 = dq * 2;
    int lmin = (m <= 31) ? (31 - m) : (m - 31);

    ull acc[4][2];
    #pragma unroll
    for (int u = 0; u < 4; u++) { acc[u][0] = 0ull; acc[u][1] = 0ull; }

    for (int jj = 0; jj < 64; jj++) {
        ulonglong2 g2 = *(const ulonglong2*)&sh_g[jj][c2];
        #pragma unroll
        for (int u = 0; u < 4; u++) {
            int l = lmin + lq + 8 * u;
            float pl = (l < 32) ? sh_P[l][jj] : 0.0f;
            ull q = pk2(pl, pl);
            acc[u][0] = ffma2(q, g2.x, acc[u][0]);
            acc[u][1] = ffma2(q, g2.y, acc[u][1]);
        }
    }
    #pragma unroll
    for (int u = 0; u < 4; u++) {
        int l = lmin + lq + 8 * u;
        if (l < 32) {
            int mm = (m - 31) + l;
            long row = (long)(32 * l * l) + b * (2 * l + 1) + mm;
            float2 r0 = upk2(acc[u][0]), r1 = upk2(acc[u][1]);
            *(float4*)&g_Ain[row * 128 + i * 64 + c2] =
                make_float4(r0.x, r0.y, r1.x, r1.y);
        }
    }
}

// ---------------------------------------------------------------------------
// k3: per-l complex GEMM on packed rows, P/Q split (unchanged — passing).
// ---------------------------------------------------------------------------
__global__ void k3_gemm(const float* __restrict__ kre, const float* __restrict__ kim) {
    __shared__ float2     sA[16][64];
    __shared__ ulonglong2 sB[16][64];

    int o = blockIdx.x, rt = blockIdx.y, l = blockIdx.z;
    int nrow = 32 * (2 * l + 1);
    int row0 = rt * 64;
    if (row0 >= nrow) return;

    int tid = threadIdx.x, tx = tid & 15, ty = tid >> 4;
    ull accP[4][4], accQ[4][4];
    #pragma unroll
    for (int ri = 0; ri < 4; ri++)
        #pragma unroll
        for (int ci = 0; ci < 4; ci++) { accP[ri][ci] = 0ull; accQ[ri][ci] = 0ull; }

    long Abase = (long)(32 * l * l) * 128;
    long wbase = (long)l * 16384 + (long)o * 4096;

    for (int k0 = 0; k0 < 128; k0 += 16) {
        #pragma unroll
        for (int t = 0; t < 4; t++) {
            int e = tid + t * 256;
            int rr = e >> 4, kk = e & 15;
            int grow = row0 + rr;
            float2 v = make_float2(0.0f, 0.0f);
            if (grow < nrow) v = g_Ain[Abase + (long)grow * 128 + k0 + kk];
            sA[kk][rr] = v;
        }
        #pragma unroll
        for (int t = 0; t < 4; t++) {
            int e = tid + t * 256;
            int kk = e >> 6, col = e & 63;
            int ic = k0 + kk;
            long a = wbase + (long)(ic >> 6) * 8192 + (ic & 63) * 64 + col;
            float br = kre[a], bim = kim[a];
            sB[kk][col] = make_ulonglong2(pk2(br, br), pk2(bim, bim));
        }
        __syncthreads();
        #pragma unroll
        for (int kk = 0; kk < 16; kk++) {
            ull av[4];
            ulonglong2 bq[4];
            #pragma unroll
            for (int u = 0; u < 4; u++) av[u] = *(const ull*)&sA[kk][ty + 16 * u];
            #pragma unroll
            for (int u = 0; u < 4; u++) bq[u] = sB[kk][tx + 16 * u];
            #pragma unroll
            for (int ri = 0; ri < 4; ri++)
                #pragma unroll
                for (int ci = 0; ci < 4; ci++) {
                    accP[ri][ci] = ffma2(bq[ci].x, av[ri], accP[ri][ci]);
                    accQ[ri][ci] = ffma2(bq[ci].y, av[ri], accQ[ri][ci]);
                }
        }
        __syncthreads();
    }
    #pragma unroll
    for (int ri = 0; ri < 4; ri++) {
        int grow = row0 + ty + 16 * ri;
        if (grow < nrow) {
            #pragma unroll
            for (int ci = 0; ci < 4; ci++)
                g_Aout[Abase + (long)grow * 128 + o * 64 + tx + 16 * ci] =
                    pq(accP[ri][ci], accQ[ri][ci]);
        }
    }
}

// ---------------------------------------------------------------------------
// k4: inverse theta. Thread owns 2 adjacent d x 8 contiguous j: per l-step
// 1 LDS.128 + 8 broadcast LDS.64 + 16 FFMA2 (was 17 LDS + 16 FFMA2).
// H[b,j,o,m,d] = sum_{l>=lmin} leg_out[o,l,m,j] * A_out[row(l,b,m-31+l), o*64+d]
// ---------------------------------------------------------------------------
__global__ void k4_itheta(const float* __restrict__ leg_out) {
    __shared__ float2 sh_a[32][64];   // [l][d]  16 KB
    __shared__ ull    sh_Q[32][64];   // [l][j] dup (q,q)  16 KB

    int m = blockIdx.x, o = blockIdx.y, b = blockIdx.z;
    int tid = threadIdx.x;
    int lmin = (m <= 31) ? (31 - m) : (m - 31);

    for (int e = tid; e < 2048; e += 256) {
        int l = e >> 6, d = e & 63;
        float2 v = make_float2(0.0f, 0.0f);
        if (l >= lmin) {
            int mm = m - 31 + l;
            long row = (long)(32 * l * l) + b * (2 * l + 1) + mm;
            v = g_Aout[row * 128 + o * 64 + d];
        }
        sh_a[l][d] = v;
    }
    for (int e = tid; e < 2048; e += 256) {
        int l = e >> 6, j = e & 63;
        float q = leg_out[((o * 32 + l) * 63 + m) * 64 + j];
        sh_Q[l][j] = pk2(q, q);
    }
    __syncthreads();

    int dq = tid & 31, jq = tid >> 5;   // d pair = {2dq, 2dq+1}; j = jq*8+u
    int d2 = dq * 2;
    int jb = jq * 8;

    ull acc[8][2];
    #pragma unroll
    for (int u = 0; u < 8; u++) { acc[u][0] = 0ull; acc[u][1] = 0ull; }

    for (int l = lmin; l < 32; l++) {
        ulonglong2 a2 = *(const ulonglong2*)&sh_a[l][d2];
        #pragma unroll
        for (int u = 0; u < 8; u++) {
            ull q = sh_Q[l][jb + u];
            acc[u][0] = ffma2(q, a2.x, acc[u][0]);
            acc[u][1] = ffma2(q, a2.y, acc[u][1]);
        }
    }
    __half2* gH = (__half2*)g_G;      // H region (fp16 complex), G is dead now
    #pragma unroll
    for (int u = 0; u < 8; u++) {
        int j = jb + u;
        long base = (long)((b * 64 + j) * 2 + o) * 4032 + m * 64 + d2;
        float2 r0 = upk2(acc[u][0]), r1 = upk2(acc[u][1]);
        __half2 h0 = __floats2half2_rn(r0.x, r0.y);
        __half2 h1 = __floats2half2_rn(r1.x, r1.y);
        uint2 st;
        st.x = *(unsigned int*)&h0;
        st.y = *(unsigned int*)&h1;
        *(uint2*)&gH[base] = st;       // base even -> 8B aligned
    }
}

// ---------------------------------------------------------------------------
// k5: inverse FFT over phi, H read as half2. X[(m-31)&63]=H[m], X[32]=0.
// ---------------------------------------------------------------------------
__global__ void k5_ifft(void* __restrict__ dout, int mode, long out_cap) {
    int bid = blockIdx.x;             // matches k4's H layout
    int d = threadIdx.x;              // 0..63

    const __half2* gH = (const __half2*)g_G;
    long hb = (long)bid * 4032 + d;
    float2 x[64];
    #pragma unroll
    for (int k = 0; k < 64; k++) {
        if (k == 32) x[k] = make_float2(0.0f, 0.0f);
        else {
            int m = (k + 31) & 63;
            x[k] = __half22float2(gH[hb + (long)m * 64]);
        }
    }
    fft64<true>(x);

    int o = bid & 1;
    long bj = (long)(bid >> 1);
    if (mode == 1) {
        float2* out2 = (float2*)dout;
        #pragma unroll
        for (int r = 0; r < 64; r++) {
            int p = bitrev6(r);
            long oi = ((bj * 64 + p) * 2 + o) * 64 + d;
            if (oi < out_cap) out2[oi] = x[r];
        }
    } else {
        float* out1 = (float*)dout;
        #pragma unroll
        for (int r = 0; r < 64; r++) {
            int p = bitrev6(r);
            long oi = ((bj * 64 + p) * 2 + o) * 64 + d;
            if (oi < out_cap) out1[oi] = x[r].x;    // real part
        }
    }
}

// ---------------------------------------------------------------------------
// Host dispatch (identical to the passing R6-R13 logic).
// ---------------------------------------------------------------------------
extern "C" void kernel_launch(void* const* d_in, const int* in_sizes, int n_in,
                              void* d_out, int out_size) {
    if (n_in < 7) return;

    const float* sph[2] = {0, 0};
    const float* ker[2] = {0, 0};
    const float* leg[2] = {0, 0};
    const float* w = 0;
    int ns = 0, nk = 0, nl = 0;

    for (int t = 0; t < n_in; t++) {
        const float* p = (const float*)d_in[t];
        int sz = in_sizes[t];
        if (sz == SZ_SPHERE && ns < 2) sph[ns++] = p;
        else if (sz == SZ_KERNEL && nk < 2) ker[nk++] = p;
        else if (sz == SZ_LEG && nl < 2) leg[nl++] = p;
        else if (sz == SZ_W && !w) w = p;
    }
    if (ns != 2 || nk != 2 || nl != 2 || !w) return;

    bool alpha = (n_in == 7 &&
                  in_sizes[0] == SZ_KERNEL && in_sizes[1] == SZ_KERNEL &&
                  in_sizes[2] == SZ_LEG    && in_sizes[3] == SZ_LEG &&
                  in_sizes[4] == SZ_W      &&
                  in_sizes[5] == SZ_SPHERE && in_sizes[6] == SZ_SPHERE);

    const float *fre, *fim, *kre, *kim;
    if (alpha) { fim = sph[0]; fre = sph[1]; kim = ker[0]; kre = ker[1]; }
    else       { fre = sph[0]; fim = sph[1]; kre = ker[0]; kim = ker[1]; }
    const float* leg_in = leg[0];
    const float* leg_out = leg[1];

    int mode;
    long cap;
    if (out_size == 33554432)      { mode = 1; cap = 16777216; }   // float2 count
    else if (out_size == 16777216) { mode = 0; cap = 16777216; }   // float count
    else                           { mode = 0; cap = (long)out_size; }

    k1_fft   <<<4096, 64>>>(fre, fim);
    k2_theta <<<dim3(63, 2, 32), 256>>>(leg_in, w);
    k3_gemm  <<<dim3(2, 32, 32), 256>>>(kre, kim);
    k4_itheta<<<dim3(63, 2, 32), 256>>>(leg_out);
    k5_ifft  <<<4096, 64>>>(d_out, mode, cap);
}

// round 15
// speedup vs baseline: 1.2528x; 1.0284x over previous
#include <cuda_runtime.h>
#include <cuda_fp16.h>

// B=32, R=64 (theta j, phi p), L=32, M=63, spins=2, C=64. All inputs f32.
#define TWO_PI_F 6.28318530717958647692f

#define SZ_SPHERE 16777216
#define SZ_KERNEL 524288
#define SZ_LEG    258048
#define SZ_W      64

// Packed (l,m): row(l,b,mm) = 32*l*l + b*(2l+1) + mm, mm = m-31+l in [0,2l].
#define N_A 4194304            // 32768*128 complex elements
#define N_G 16515072           // region sized in float2; G and H live here as half2

__device__ float2 g_G   [N_G];  // used as __half2[] for both G and H phases
__device__ float2 g_Ain [N_A];  // used as __half2[] (fp16 complex)
__device__ float2 g_Aout[N_A];  // used as __half2[] (fp16 complex)

typedef unsigned long long ull;

__device__ __forceinline__ ull pk2(float lo, float hi) {
    ull r; asm("mov.b64 %0, {%1,%2};" : "=l"(r) : "f"(lo), "f"(hi)); return r;
}
__device__ __forceinline__ ull ffma2(ull a, ull b, ull c) {
    ull d; asm("fma.rn.f32x2 %0, %1, %2, %3;" : "=l"(d) : "l"(a), "l"(b), "l"(c)); return d;
}
__device__ __forceinline__ float2 upk2(ull v) {
    float2 f; asm("mov.b64 {%0,%1}, %2;" : "=f"(f.x), "=f"(f.y) : "l"(v)); return f;
}
__device__ __forceinline__ float2 pq(ull P, ull Q) {
    float2 p = upk2(P), q = upk2(Q);
    return make_float2(p.x - q.y, p.y + q.x);
}
__device__ __forceinline__ unsigned int h2u(float2 v) {
    __half2 h = __floats2half2_rn(v.x, v.y);
    return *(unsigned int*)&h;
}

// ---------------------------------------------------------------------------
// FFT-64: radix-2 DIF, natural input -> bit-reversed output.
// ---------------------------------------------------------------------------
__constant__ float cW[32] = {
    1.0f, 0.99518472667f, 0.98078528040f, 0.95694033573f,
    0.92387953251f, 0.88192126435f, 0.83146961230f, 0.77301045336f,
    0.70710678119f, 0.63439328416f, 0.55557023302f, 0.47139673683f,
    0.38268343236f, 0.29028467725f, 0.19509032202f, 0.09801714033f,
    0.0f, -0.09801714033f, -0.19509032202f, -0.29028467725f,
    -0.38268343236f, -0.47139673683f, -0.55557023302f, -0.63439328416f,
    -0.70710678119f, -0.77301045336f, -0.83146961230f, -0.88192126435f,
    -0.92387953251f, -0.95694033573f, -0.98078528040f, -0.99518472667f };
__constant__ float sW[32] = {
    0.0f, 0.09801714033f, 0.19509032202f, 0.29028467725f,
    0.38268343236f, 0.47139673683f, 0.55557023302f, 0.63439328416f,
    0.70710678119f, 0.77301045336f, 0.83146961230f, 0.88192126435f,
    0.92387953251f, 0.95694033573f, 0.98078528040f, 0.99518472667f,
    1.0f, 0.99518472667f, 0.98078528040f, 0.95694033573f,
    0.92387953251f, 0.88192126435f, 0.83146961230f, 0.77301045336f,
    0.70710678119f, 0.63439328416f, 0.55557023302f, 0.47139673683f,
    0.38268343236f, 0.29028467725f, 0.19509032202f, 0.09801714033f };

__device__ __forceinline__ constexpr int bitrev6(int i) {
    return ((i & 1) << 5) | ((i & 2) << 3) | ((i & 4) << 1)
         | ((i & 8) >> 1) | ((i & 16) >> 3) | ((i & 32) >> 5);
}

template <int LEN, bool INV>
__device__ __forceinline__ void fft_stage(float2* x) {
    constexpr int HALF = LEN / 2;
    constexpr int STEP = 64 / LEN;
    #pragma unroll
    for (int st = 0; st < 64; st += LEN) {
        #pragma unroll
        for (int k = 0; k < HALF; k++) {
            float2 u = x[st + k], v = x[st + k + HALF];
            x[st + k] = make_float2(u.x + v.x, u.y + v.y);
            float2 t = make_float2(u.x - v.x, u.y - v.y);
            if (k == 0) {
                x[st + k + HALF] = t;
            } else {
                float wr = cW[k * STEP];
                float wi = INV ? sW[k * STEP] : -sW[k * STEP];
                x[st + k + HALF] = make_float2(t.x * wr - t.y * wi,
                                               t.x * wi + t.y * wr);
            }
        }
    }
}

template <bool INV>
__device__ __forceinline__ void fft64(float2* x) {
    fft_stage<64, INV>(x);
    fft_stage<32, INV>(x);
    fft_stage<16, INV>(x);
    fft_stage<8,  INV>(x);
    fft_stage<4,  INV>(x);
    fft_stage<2,  INV>(x);
}

// ---------------------------------------------------------------------------
// k1: forward FFT over phi. G[b,i,m,j,c] = X[(m-31)&63]/64, X = fft_p(f).
// G stored as half2 (fp16 complex).
// ---------------------------------------------------------------------------
__global__ void k1_fft(const float* __restrict__ fre, const float* __restrict__ fim) {
    int bid = blockIdx.x;
    int j = bid & 63, bi = bid >> 6;
    int i = bi & 1,  b = bi >> 1;
    int c = threadIdx.x;   // 0..63

    long base = (long)(b * 64 + j) * 8192 + i * 64 + c;   // + p*128
    float2 x[64];
    #pragma unroll
    for (int p = 0; p < 64; p++) {
        long a = base + (long)p * 128;
        x[p] = make_float2(fre[a] * (1.0f / 64.0f), fim[a] * (1.0f / 64.0f));
    }
    fft64<false>(x);

    __half2* gG = (__half2*)g_G;
    long gb = (long)bi * 63 * 4096 + (long)j * 64 + c;
    #pragma unroll
    for (int r = 0; r < 64; r++) {
        int k = bitrev6(r);
        if (k != 32) {                       // m==63 bin doesn't exist
            int m = (k + 31) & 63;
            gG[gb + (long)m * 4096] = __floats2half2_rn(x[r].x, x[r].y);
        }
    }
}

// ---------------------------------------------------------------------------
// k2: theta quadrature, packed output (R14 mapping: 2 adjacent c x 4 strided l).
// A_in stored as half2 (fp16 complex).
// A_in[row(l,b,mm), i*64+c] = sum_j (2pi w_j leg_in[i,l,m,j]) G[b,i,m,j,c]
// ---------------------------------------------------------------------------
__global__ void k2_theta(const float* __restrict__ leg_in, const float* __restrict__ w) {
    __shared__ float2 sh_g[64][64];   // [j][c]  32 KB
    __shared__ float  sh_P[32][64];   // [l][j]   8 KB

    int m = blockIdx.x, i = blockIdx.y, b = blockIdx.z;
    int tid = threadIdx.x;
    int bi = b * 2 + i;

    const __half2* gG = (const __half2*)g_G;
    long gbase = ((long)bi * 63 + m) * 4096;
    for (int e = tid; e < 4096; e += 256)
        sh_g[e >> 6][e & 63] = __half22float2(gG[gbase + e]);
    for (int e = tid; e < 2048; e += 256) {
        int l = e >> 6, jj = e & 63;
        sh_P[l][jj] = TWO_PI_F * w[jj] * leg_in[((i * 32 + l) * 63 + m) * 64 + jj];
    }
    __syncthreads();

    int dq = tid & 31, lq = tid >> 5;   // c pair = {2dq, 2dq+1}; l = lmin+lq+8u
    int c2 = dq * 2;
    int lmin = (m <= 31) ? (31 - m) : (m - 31);

    ull acc[4][2];
    #pragma unroll
    for (int u = 0; u < 4; u++) { acc[u][0] = 0ull; acc[u][1] = 0ull; }

    for (int jj = 0; jj < 64; jj++) {
        ulonglong2 g2 = *(const ulonglong2*)&sh_g[jj][c2];
        #pragma unroll
        for (int u = 0; u < 4; u++) {
            int l = lmin + lq + 8 * u;
            float pl = (l < 32) ? sh_P[l][jj] : 0.0f;
            ull q = pk2(pl, pl);
            acc[u][0] = ffma2(q, g2.x, acc[u][0]);
            acc[u][1] = ffma2(q, g2.y, acc[u][1]);
        }
    }
    __half2* gA = (__half2*)g_Ain;
    #pragma unroll
    for (int u = 0; u < 4; u++) {
        int l = lmin + lq + 8 * u;
        if (l < 32) {
            int mm = (m - 31) + l;
            long row = (long)(32 * l * l) + b * (2 * l + 1) + mm;
            uint2 st;
            st.x = h2u(upk2(acc[u][0]));
            st.y = h2u(upk2(acc[u][1]));
            *(uint2*)&gA[row * 128 + i * 64 + c2] = st;   // 8B aligned (c2 even)
        }
    }
}

// ---------------------------------------------------------------------------
// k3: per-l complex GEMM on packed rows, P/Q split. A_in/A_out global as fp16;
// shared tiles and math unchanged (fp32 FFMA2).
// ---------------------------------------------------------------------------
__global__ void k3_gemm(const float* __restrict__ kre, const float* __restrict__ kim) {
    __shared__ float2     sA[16][64];
    __shared__ ulonglong2 sB[16][64];

    int o = blockIdx.x, rt = blockIdx.y, l = blockIdx.z;
    int nrow = 32 * (2 * l + 1);
    int row0 = rt * 64;
    if (row0 >= nrow) return;

    int tid = threadIdx.x, tx = tid & 15, ty = tid >> 4;
    ull accP[4][4], accQ[4][4];
    #pragma unroll
    for (int ri = 0; ri < 4; ri++)
        #pragma unroll
        for (int ci = 0; ci < 4; ci++) { accP[ri][ci] = 0ull; accQ[ri][ci] = 0ull; }

    const __half2* gAin = (const __half2*)g_Ain;
    __half2* gAout = (__half2*)g_Aout;
    long Abase = (long)(32 * l * l) * 128;
    long wbase = (long)l * 16384 + (long)o * 4096;

    for (int k0 = 0; k0 < 128; k0 += 16) {
        #pragma unroll
        for (int t = 0; t < 4; t++) {
            int e = tid + t * 256;
            int rr = e >> 4, kk = e & 15;
            int grow = row0 + rr;
            float2 v = make_float2(0.0f, 0.0f);
            if (grow < nrow) v = __half22float2(gAin[Abase + (long)grow * 128 + k0 + kk]);
            sA[kk][rr] = v;
        }
        #pragma unroll
        for (int t = 0; t < 4; t++) {
            int e = tid + t * 256;
            int kk = e >> 6, col = e & 63;
            int ic = k0 + kk;
            long a = wbase + (long)(ic >> 6) * 8192 + (ic & 63) * 64 + col;
            float br = kre[a], bim = kim[a];
            sB[kk][col] = make_ulonglong2(pk2(br, br), pk2(bim, bim));
        }
        __syncthreads();
        #pragma unroll
        for (int kk = 0; kk < 16; kk++) {
            ull av[4];
            ulonglong2 bq[4];
            #pragma unroll
            for (int u = 0; u < 4; u++) av[u] = *(const ull*)&sA[kk][ty + 16 * u];
            #pragma unroll
            for (int u = 0; u < 4; u++) bq[u] = sB[kk][tx + 16 * u];
            #pragma unroll
            for (int ri = 0; ri < 4; ri++)
                #pragma unroll
                for (int ci = 0; ci < 4; ci++) {
                    accP[ri][ci] = ffma2(bq[ci].x, av[ri], accP[ri][ci]);
                    accQ[ri][ci] = ffma2(bq[ci].y, av[ri], accQ[ri][ci]);
                }
        }
        __syncthreads();
    }
    #pragma unroll
    for (int ri = 0; ri < 4; ri++) {
        int grow = row0 + ty + 16 * ri;
        if (grow < nrow) {
            #pragma unroll
            for (int ci = 0; ci < 4; ci++) {
                float2 r = pq(accP[ri][ci], accQ[ri][ci]);
                gAout[Abase + (long)grow * 128 + o * 64 + tx + 16 * ci] =
                    __floats2half2_rn(r.x, r.y);
            }
        }
    }
}

// ---------------------------------------------------------------------------
// k4: inverse theta — R12-exact shapes (the 63 us champion config):
// d = tid&63, 16 strided j accumulators, fp16 H store, no launch_bounds.
// A_out now read as fp16.
// H[b,j,o,m,d] = sum_{l>=lmin} leg_out[o,l,m,j] * A_out[row(l,b,m-31+l), o*64+d]
// ---------------------------------------------------------------------------
__global__ void k4_itheta(const float* __restrict__ leg_out) {
    __shared__ float2 sh_a[32][64];   // [l][d]
    __shared__ ull    sh_Q[32][64];   // [l][j] dup (q,q)

    int m = blockIdx.x, o = blockIdx.y, b = blockIdx.z;
    int tid = threadIdx.x;
    int lmin = (m <= 31) ? (31 - m) : (m - 31);

    const __half2* gAout = (const __half2*)g_Aout;
    for (int e = tid; e < 2048; e += 256) {
        int l = e >> 6, d = e & 63;
        float2 v = make_float2(0.0f, 0.0f);
        if (l >= lmin) {
            int mm = m - 31 + l;
            long row = (long)(32 * l * l) + b * (2 * l + 1) + mm;
            v = __half22float2(gAout[row * 128 + o * 64 + d]);
        }
        sh_a[l][d] = v;
    }
    for (int e = tid; e < 2048; e += 256) {
        int l = e >> 6, j = e & 63;
        float q = leg_out[((o * 32 + l) * 63 + m) * 64 + j];
        sh_Q[l][j] = pk2(q, q);
    }
    __syncthreads();

    int d = tid & 63, jq = tid >> 6;
    ull acc[16];
    #pragma unroll
    for (int u = 0; u < 16; u++) acc[u] = 0ull;

    for (int l = lmin; l < 32; l++) {
        ull a = *(const ull*)&sh_a[l][d];
        #pragma unroll
        for (int u = 0; u < 16; u++)
            acc[u] = ffma2(sh_Q[l][jq + 4 * u], a, acc[u]);
    }
    __half2* gH = (__half2*)g_G;      // H region (fp16 complex), G is dead now
    #pragma unroll
    for (int u = 0; u < 16; u++) {
        int j = jq + 4 * u;
        float2 r = upk2(acc[u]);
        gH[(long)((b * 64 + j) * 2 + o) * 4032 + m * 64 + d] =
            __floats2half2_rn(r.x, r.y);
    }
}

// ---------------------------------------------------------------------------
// k5: inverse FFT over phi, H read as half2. X[(m-31)&63]=H[m], X[32]=0.
// ---------------------------------------------------------------------------
__global__ void k5_ifft(void* __restrict__ dout, int mode, long out_cap) {
    int bid = blockIdx.x;             // matches k4's H layout
    int d = threadIdx.x;              // 0..63

    const __half2* gH = (const __half2*)g_G;
    long hb = (long)bid * 4032 + d;
    float2 x[64];
    #pragma unroll
    for (int k = 0; k < 64; k++) {
        if (k == 32) x[k] = make_float2(0.0f, 0.0f);
        else {
            int m = (k + 31) & 63;
            x[k] = __half22float2(gH[hb + (long)m * 64]);
        }
    }
    fft64<true>(x);

    int o = bid & 1;
    long bj = (long)(bid >> 1);
    if (mode == 1) {
        float2* out2 = (float2*)dout;
        #pragma unroll
        for (int r = 0; r < 64; r++) {
            int p = bitrev6(r);
            long oi = ((bj * 64 + p) * 2 + o) * 64 + d;
            if (oi < out_cap) out2[oi] = x[r];
        }
    } else {
        float* out1 = (float*)dout;
        #pragma unroll
        for (int r = 0; r < 64; r++) {
            int p = bitrev6(r);
            long oi = ((bj * 64 + p) * 2 + o) * 64 + d;
            if (oi < out_cap) out1[oi] = x[r].x;    // real part
        }
    }
}

// ---------------------------------------------------------------------------
// Host dispatch (identical to the passing R6-R14 logic).
// ---------------------------------------------------------------------------
extern "C" void kernel_launch(void* const* d_in, const int* in_sizes, int n_in,
                              void* d_out, int out_size) {
    if (n_in < 7) return;

    const float* sph[2] = {0, 0};
    const float* ker[2] = {0, 0};
    const float* leg[2] = {0, 0};
    const float* w = 0;
    int ns = 0, nk = 0, nl = 0;

    for (int t = 0; t < n_in; t++) {
        const float* p = (const float*)d_in[t];
        int sz = in_sizes[t];
        if (sz == SZ_SPHERE && ns < 2) sph[ns++] = p;
        else if (sz == SZ_KERNEL && nk < 2) ker[nk++] = p;
        else if (sz == SZ_LEG && nl < 2) leg[nl++] = p;
        else if (sz == SZ_W && !w) w = p;
    }
    if (ns != 2 || nk != 2 || nl != 2 || !w) return;

    bool alpha = (n_in == 7 &&
                  in_sizes[0] == SZ_KERNEL && in_sizes[1] == SZ_KERNEL &&
                  in_sizes[2] == SZ_LEG    && in_sizes[3] == SZ_LEG &&
                  in_sizes[4] == SZ_W      &&
                  in_sizes[5] == SZ_SPHERE && in_sizes[6] == SZ_SPHERE);

    const float *fre, *fim, *kre, *kim;
    if (alpha) { fim = sph[0]; fre = sph[1]; kim = ker[0]; kre = ker[1]; }
    else       { fre = sph[0]; fim = sph[1]; kre = ker[0]; kim = ker[1]; }
    const float* leg_in = leg[0];
    const float* leg_out = leg[1];

    int mode;
    long cap;
    if (out_size == 33554432)      { mode = 1; cap = 16777216; }   // float2 count
    else if (out_size == 16777216) { mode = 0; cap = 16777216; }   // float count
    else                           { mode = 0; cap = (long)out_size; }

    k1_fft   <<<4096, 64>>>(fre, fim);
    k2_theta <<<dim3(63, 2, 32), 256>>>(leg_in, w);
    k3_gemm  <<<dim3(2, 32, 32), 256>>>(kre, kim);
    k4_itheta<<<dim3(63, 2, 32), 256>>>(leg_out);
    k5_ifft  <<<4096, 64>>>(d_out, mode, cap);
}

// round 16
// speedup vs baseline: 1.5139x; 1.2084x over previous
#include <cuda_runtime.h>
#include <cuda_fp16.h>

// B=32, R=64 (theta j, phi p), L=32, M=63, spins=2, C=64. All inputs f32.
#define TWO_PI_F 6.28318530717958647692f

#define SZ_SPHERE 16777216
#define SZ_KERNEL 524288
#define SZ_LEG    258048
#define SZ_W      64

// Packed (l,m): row(l,b,mm) = 32*l*l + b*(2l+1) + mm, mm = m-31+l in [0,2l].
#define N_A 4194304            // 32768*128 complex elements
#define N_G 16515072           // region sized in float2; G and H live here as half2

__device__ float2 g_G   [N_G];  // used as __half2[] for both G and H phases
__device__ float2 g_Ain [N_A];  // used as __half2[] (fp16 complex)
__device__ float2 g_Aout[N_A];  // used as __half2[] (fp16 complex)

typedef unsigned long long ull;

__device__ __forceinline__ ull pk2(float lo, float hi) {
    ull r; asm("mov.b64 %0, {%1,%2};" : "=l"(r) : "f"(lo), "f"(hi)); return r;
}
__device__ __forceinline__ ull ffma2(ull a, ull b, ull c) {
    ull d; asm("fma.rn.f32x2 %0, %1, %2, %3;" : "=l"(d) : "l"(a), "l"(b), "l"(c)); return d;
}
__device__ __forceinline__ float2 upk2(ull v) {
    float2 f; asm("mov.b64 {%0,%1}, %2;" : "=f"(f.x), "=f"(f.y) : "l"(v)); return f;
}
__device__ __forceinline__ unsigned int h2u(float2 v) {
    __half2 h = __floats2half2_rn(v.x, v.y);
    return *(unsigned int*)&h;
}

// ---------------------------------------------------------------------------
// FFT-64: radix-2 DIF, natural input -> bit-reversed output.
// ---------------------------------------------------------------------------
__constant__ float cW[32] = {
    1.0f, 0.99518472667f, 0.98078528040f, 0.95694033573f,
    0.92387953251f, 0.88192126435f, 0.83146961230f, 0.77301045336f,
    0.70710678119f, 0.63439328416f, 0.55557023302f, 0.47139673683f,
    0.38268343236f, 0.29028467725f, 0.19509032202f, 0.09801714033f,
    0.0f, -0.09801714033f, -0.19509032202f, -0.29028467725f,
    -0.38268343236f, -0.47139673683f, -0.55557023302f, -0.63439328416f,
    -0.70710678119f, -0.77301045336f, -0.83146961230f, -0.88192126435f,
    -0.92387953251f, -0.95694033573f, -0.98078528040f, -0.99518472667f };
__constant__ float sW[32] = {
    0.0f, 0.09801714033f, 0.19509032202f, 0.29028467725f,
    0.38268343236f, 0.47139673683f, 0.55557023302f, 0.63439328416f,
    0.70710678119f, 0.77301045336f, 0.83146961230f, 0.88192126435f,
    0.92387953251f, 0.95694033573f, 0.98078528040f, 0.99518472667f,
    1.0f, 0.99518472667f, 0.98078528040f, 0.95694033573f,
    0.92387953251f, 0.88192126435f, 0.83146961230f, 0.77301045336f,
    0.70710678119f, 0.63439328416f, 0.55557023302f, 0.47139673683f,
    0.38268343236f, 0.29028467725f, 0.19509032202f, 0.09801714033f };

__device__ __forceinline__ constexpr int bitrev6(int i) {
    return ((i & 1) << 5) | ((i & 2) << 3) | ((i & 4) << 1)
         | ((i & 8) >> 1) | ((i & 16) >> 3) | ((i & 32) >> 5);
}

template <int LEN, bool INV>
__device__ __forceinline__ void fft_stage(float2* x) {
    constexpr int HALF = LEN / 2;
    constexpr int STEP = 64 / LEN;
    #pragma unroll
    for (int st = 0; st < 64; st += LEN) {
        #pragma unroll
        for (int k = 0; k < HALF; k++) {
            float2 u = x[st + k], v = x[st + k + HALF];
            x[st + k] = make_float2(u.x + v.x, u.y + v.y);
            float2 t = make_float2(u.x - v.x, u.y - v.y);
            if (k == 0) {
                x[st + k + HALF] = t;
            } else {
                float wr = cW[k * STEP];
                float wi = INV ? sW[k * STEP] : -sW[k * STEP];
                x[st + k + HALF] = make_float2(t.x * wr - t.y * wi,
                                               t.x * wi + t.y * wr);
            }
        }
    }
}

template <bool INV>
__device__ __forceinline__ void fft64(float2* x) {
    fft_stage<64, INV>(x);
    fft_stage<32, INV>(x);
    fft_stage<16, INV>(x);
    fft_stage<8,  INV>(x);
    fft_stage<4,  INV>(x);
    fft_stage<2,  INV>(x);
}

// ---------------------------------------------------------------------------
// k1: forward FFT over phi. G[b,i,m,j,c] = X[(m-31)&63]/64, X = fft_p(f).
// G stored as half2 (fp16 complex).
// ---------------------------------------------------------------------------
__global__ void k1_fft(const float* __restrict__ fre, const float* __restrict__ fim) {
    int bid = blockIdx.x;
    int j = bid & 63, bi = bid >> 6;
    int i = bi & 1,  b = bi >> 1;
    int c = threadIdx.x;   // 0..63

    long base = (long)(b * 64 + j) * 8192 + i * 64 + c;   // + p*128
    float2 x[64];
    #pragma unroll
    for (int p = 0; p < 64; p++) {
        long a = base + (long)p * 128;
        x[p] = make_float2(fre[a] * (1.0f / 64.0f), fim[a] * (1.0f / 64.0f));
    }
    fft64<false>(x);

    __half2* gG = (__half2*)g_G;
    long gb = (long)bi * 63 * 4096 + (long)j * 64 + c;
    #pragma unroll
    for (int r = 0; r < 64; r++) {
        int k = bitrev6(r);
        if (k != 32) {                       // m==63 bin doesn't exist
            int m = (k + 31) & 63;
            gG[gb + (long)m * 4096] = __floats2half2_rn(x[r].x, x[r].y);
        }
    }
}

// ---------------------------------------------------------------------------
// k2: theta quadrature, packed output (R14/R15 shape).
// A_in stored as half2 (fp16 complex).
// ---------------------------------------------------------------------------
__global__ void k2_theta(const float* __restrict__ leg_in, const float* __restrict__ w) {
    __shared__ float2 sh_g[64][64];   // [j][c]  32 KB
    __shared__ float  sh_P[32][64];   // [l][j]   8 KB

    int m = blockIdx.x, i = blockIdx.y, b = blockIdx.z;
    int tid = threadIdx.x;
    int bi = b * 2 + i;

    const __half2* gG = (const __half2*)g_G;
    long gbase = ((long)bi * 63 + m) * 4096;
    for (int e = tid; e < 4096; e += 256)
        sh_g[e >> 6][e & 63] = __half22float2(gG[gbase + e]);
    for (int e = tid; e < 2048; e += 256) {
        int l = e >> 6, jj = e & 63;
        sh_P[l][jj] = TWO_PI_F * w[jj] * leg_in[((i * 32 + l) * 63 + m) * 64 + jj];
    }
    __syncthreads();

    int dq = tid & 31, lq = tid >> 5;
    int c2 = dq * 2;
    int lmin = (m <= 31) ? (31 - m) : (m - 31);

    ull acc[4][2];
    #pragma unroll
    for (int u = 0; u < 4; u++) { acc[u][0] = 0ull; acc[u][1] = 0ull; }

    for (int jj = 0; jj < 64; jj++) {
        ulonglong2 g2 = *(const ulonglong2*)&sh_g[jj][c2];
        #pragma unroll
        for (int u = 0; u < 4; u++) {
            int l = lmin + lq + 8 * u;
            float pl = (l < 32) ? sh_P[l][jj] : 0.0f;
            ull q = pk2(pl, pl);
            acc[u][0] = ffma2(q, g2.x, acc[u][0]);
            acc[u][1] = ffma2(q, g2.y, acc[u][1]);
        }
    }
    __half2* gA = (__half2*)g_Ain;
    #pragma unroll
    for (int u = 0; u < 4; u++) {
        int l = lmin + lq + 8 * u;
        if (l < 32) {
            int mm = (m - 31) + l;
            long row = (long)(32 * l * l) + b * (2 * l + 1) + mm;
            uint2 st;
            st.x = h2u(upk2(acc[u][0]));
            st.y = h2u(upk2(acc[u][1]));
            *(uint2*)&gA[row * 128 + i * 64 + c2] = st;
        }
    }
}

// ---------------------------------------------------------------------------
// k3: per-l GEMM on tensor cores (HMMA m16n8k16, f16 in / f32 acc).
// Real-ified: A = g_Ain viewed as M x 256 fp16 row-major (re,im interleaved).
// W[2ic+s][2od+t] = [[kr, ki], [-ki, kr]]; D = A*W gives interleaved (re,im).
// Block: 8 warps (4m x 2n), BM=64 rows, BN=128 real cols (=64 complex od),
// BK=32 real. Grid (on=2, rt=32, l=32); rt > l exits (nrow = 64l+32).
// ---------------------------------------------------------------------------
__global__ void k3_gemm(const float* __restrict__ kre, const float* __restrict__ kim) {
    __shared__ __half sA[64][40];     // A tile: 64 rows x 32 real k (+8 pad)
    __shared__ __half sW2[128][40];   // W tile transposed: [n_real][k_real]

    int on = blockIdx.x, rt = blockIdx.y, l = blockIdx.z;
    if (rt > l) return;                      // nrow = 64l+32 -> l+1 row tiles
    int nrow = 32 * (2 * l + 1);
    int row0 = rt * 64;

    int tid = threadIdx.x;
    int lane = tid & 31, wid = tid >> 5;
    int warp_m = wid & 3, warp_n = wid >> 2;
    int g = lane >> 2, tig = lane & 3;

    const __half2* gAin = (const __half2*)g_Ain;
    __half2* gAout = (__half2*)g_Aout;
    long Abase = (long)(32 * l * l) * 128;
    long wbase = (long)l * 16384 + (long)on * 4096;   // + i*8192 + c*64 + d

    float acc[8][4];
    #pragma unroll
    for (int nt = 0; nt < 8; nt++)
        #pragma unroll
        for (int q = 0; q < 4; q++) acc[nt][q] = 0.0f;

    for (int it = 0; it < 8; it++) {          // K loop: 16 complex per iter
        int kc0 = it * 16;
        // A tile: 64 rows x 16 complex (=32 real halves)
        #pragma unroll
        for (int t = 0; t < 4; t++) {
            int idx = tid + t * 256;
            int rr = idx >> 4, cc = idx & 15;
            int grow = row0 + rr;
            __half2 v = __floats2half2_rn(0.0f, 0.0f);
            if (grow < nrow) v = gAin[Abase + (long)grow * 128 + kc0 + cc];
            *(__half2*)&sA[rr][cc * 2] = v;
        }
        // W tile: 16 complex ic x 64 complex od -> [128 real n][32 real k]
        #pragma unroll
        for (int t = 0; t < 4; t++) {
            int idx = tid + t * 256;
            int od_l = idx >> 4, ic_l = idx & 15;
            int ic = kc0 + ic_l;
            long a = wbase + (long)(ic >> 6) * 8192 + (ic & 63) * 64 + od_l;
            float kr = kre[a], ki = kim[a];
            *(__half2*)&sW2[od_l * 2][ic_l * 2]     = __floats2half2_rn(kr, -ki);
            *(__half2*)&sW2[od_l * 2 + 1][ic_l * 2] = __floats2half2_rn(ki, kr);
        }
        __syncthreads();

        int ar = warp_m * 16 + g;
        #pragma unroll
        for (int kt = 0; kt < 2; kt++) {
            int kc = kt * 16 + tig * 2;
            unsigned int a0 = *(unsigned int*)&sA[ar][kc];
            unsigned int a1 = *(unsigned int*)&sA[ar + 8][kc];
            unsigned int a2 = *(unsigned int*)&sA[ar][kc + 8];
            unsigned int a3 = *(unsigned int*)&sA[ar + 8][kc + 8];
            #pragma unroll
            for (int nt = 0; nt < 8; nt++) {
                int bn = warp_n * 64 + nt * 8 + g;
                unsigned int b0 = *(unsigned int*)&sW2[bn][kc];
                unsigned int b1 = *(unsigned int*)&sW2[bn][kc + 8];
                asm volatile(
                    "mma.sync.aligned.m16n8k16.row.col.f32.f16.f16.f32 "
                    "{%0,%1,%2,%3}, {%4,%5,%6,%7}, {%8,%9}, {%0,%1,%2,%3};"
                    : "+f"(acc[nt][0]), "+f"(acc[nt][1]),
                      "+f"(acc[nt][2]), "+f"(acc[nt][3])
                    : "r"(a0), "r"(a1), "r"(a2), "r"(a3), "r"(b0), "r"(b1));
            }
        }
        __syncthreads();
    }

    // Store: (c0,c1) = (re,im) of complex od, rows g and g+8.
    int grow0 = row0 + warp_m * 16 + g;
    int grow1 = grow0 + 8;
    #pragma unroll
    for (int nt = 0; nt < 8; nt++) {
        int od_l = warp_n * 32 + nt * 4 + tig;     // complex col within 64
        long colbase = Abase + (long)on * 64 + od_l;
        if (grow0 < nrow)
            gAout[colbase + (long)grow0 * 128] = __floats2half2_rn(acc[nt][0], acc[nt][1]);
        if (grow1 < nrow)
            gAout[colbase + (long)grow1 * 128] = __floats2half2_rn(acc[nt][2], acc[nt][3]);
    }
}

// ---------------------------------------------------------------------------
// k4: inverse theta — R12/R15 champion shapes. A_out read as fp16.
// ---------------------------------------------------------------------------
__global__ void k4_itheta(const float* __restrict__ leg_out) {
    __shared__ float2 sh_a[32][64];   // [l][d]
    __shared__ ull    sh_Q[32][64];   // [l][j] dup (q,q)

    int m = blockIdx.x, o = blockIdx.y, b = blockIdx.z;
    int tid = threadIdx.x;
    int lmin = (m <= 31) ? (31 - m) : (m - 31);

    const __half2* gAout = (const __half2*)g_Aout;
    for (int e = tid; e < 2048; e += 256) {
        int l = e >> 6, d = e & 63;
        float2 v = make_float2(0.0f, 0.0f);
        if (l >= lmin) {
            int mm = m - 31 + l;
            long row = (long)(32 * l * l) + b * (2 * l + 1) + mm;
            v = __half22float2(gAout[row * 128 + o * 64 + d]);
        }
        sh_a[l][d] = v;
    }
    for (int e = tid; e < 2048; e += 256) {
        int l = e >> 6, j = e & 63;
        float q = leg_out[((o * 32 + l) * 63 + m) * 64 + j];
        sh_Q[l][j] = pk2(q, q);
    }
    __syncthreads();

    int d = tid & 63, jq = tid >> 6;
    ull acc[16];
    #pragma unroll
    for (int u = 0; u < 16; u++) acc[u] = 0ull;

    for (int l = lmin; l < 32; l++) {
        ull a = *(const ull*)&sh_a[l][d];
        #pragma unroll
        for (int u = 0; u < 16; u++)
            acc[u] = ffma2(sh_Q[l][jq + 4 * u], a, acc[u]);
    }
    __half2* gH = (__half2*)g_G;      // H region (fp16 complex), G is dead now
    #pragma unroll
    for (int u = 0; u < 16; u++) {
        int j = jq + 4 * u;
        float2 r = upk2(acc[u]);
        gH[(long)((b * 64 + j) * 2 + o) * 4032 + m * 64 + d] =
            __floats2half2_rn(r.x, r.y);
    }
}

// ---------------------------------------------------------------------------
// k5: inverse FFT over phi, H read as half2. X[(m-31)&63]=H[m], X[32]=0.
// ---------------------------------------------------------------------------
__global__ void k5_ifft(void* __restrict__ dout, int mode, long out_cap) {
    int bid = blockIdx.x;             // matches k4's H layout
    int d = threadIdx.x;              // 0..63

    const __half2* gH = (const __half2*)g_G;
    long hb = (long)bid * 4032 + d;
    float2 x[64];
    #pragma unroll
    for (int k = 0; k < 64; k++) {
        if (k == 32) x[k] = make_float2(0.0f, 0.0f);
        else {
            int m = (k + 31) & 63;
            x[k] = __half22float2(gH[hb + (long)m * 64]);
        }
    }
    fft64<true>(x);

    int o = bid & 1;
    long bj = (long)(bid >> 1);
    if (mode == 1) {
        float2* out2 = (float2*)dout;
        #pragma unroll
        for (int r = 0; r < 64; r++) {
            int p = bitrev6(r);
            long oi = ((bj * 64 + p) * 2 + o) * 64 + d;
            if (oi < out_cap) out2[oi] = x[r];
        }
    } else {
        float* out1 = (float*)dout;
        #pragma unroll
        for (int r = 0; r < 64; r++) {
            int p = bitrev6(r);
            long oi = ((bj * 64 + p) * 2 + o) * 64 + d;
            if (oi < out_cap) out1[oi] = x[r].x;    // real part
        }
    }
}

// ---------------------------------------------------------------------------
// Host dispatch (identical to the passing R6-R15 logic).
// ---------------------------------------------------------------------------
extern "C" void kernel_launch(void* const* d_in, const int* in_sizes, int n_in,
                              void* d_out, int out_size) {
    if (n_in < 7) return;

    const float* sph[2] = {0, 0};
    const float* ker[2] = {0, 0};
    const float* leg[2] = {0, 0};
    const float* w = 0;
    int ns = 0, nk = 0, nl = 0;

    for (int t = 0; t < n_in; t++) {
        const float* p = (const float*)d_in[t];
        int sz = in_sizes[t];
        if (sz == SZ_SPHERE && ns < 2) sph[ns++] = p;
        else if (sz == SZ_KERNEL && nk < 2) ker[nk++] = p;
        else if (sz == SZ_LEG && nl < 2) leg[nl++] = p;
        else if (sz == SZ_W && !w) w = p;
    }
    if (ns != 2 || nk != 2 || nl != 2 || !w) return;

    bool alpha = (n_in == 7 &&
                  in_sizes[0] == SZ_KERNEL && in_sizes[1] == SZ_KERNEL &&
                  in_sizes[2] == SZ_LEG    && in_sizes[3] == SZ_LEG &&
                  in_sizes[4] == SZ_W      &&
                  in_sizes[5] == SZ_SPHERE && in_sizes[6] == SZ_SPHERE);

    const float *fre, *fim, *kre, *kim;
    if (alpha) { fim = sph[0]; fre = sph[1]; kim = ker[0]; kre = ker[1]; }
    else       { fre = sph[0]; fim = sph[1]; kre = ker[0]; kim = ker[1]; }
    const float* leg_in = leg[0];
    const float* leg_out = leg[1];

    int mode;
    long cap;
    if (out_size == 33554432)      { mode = 1; cap = 16777216; }   // float2 count
    else if (out_size == 16777216) { mode = 0; cap = 16777216; }   // float count
    else                           { mode = 0; cap = (long)out_size; }

    k1_fft   <<<4096, 64>>>(fre, fim);
    k2_theta <<<dim3(63, 2, 32), 256>>>(leg_in, w);
    k3_gemm  <<<dim3(2, 32, 32), 256>>>(kre, kim);
    k4_itheta<<<dim3(63, 2, 32), 256>>>(leg_out);
    k5_ifft  <<<4096, 64>>>(d_out, mode, cap);
}

// round 17
// speedup vs baseline: 1.8911x; 1.2491x over previous
#include <cuda_runtime.h>
#include <cuda_fp16.h>

// B=32, R=64 (theta j, phi p), L=32, M=63, spins=2, C=64. All inputs f32.
#define TWO_PI_F 6.28318530717958647692f

#define SZ_SPHERE 16777216
#define SZ_KERNEL 524288
#define SZ_LEG    258048
#define SZ_W      64

// Packed (l,m): row(l,b,mm) = 32*l*l + b*(2l+1) + mm, mm = m-31+l in [0,2l].
#define N_A 4194304            // 32768*128 complex elements
#define N_G 16515072           // region sized in float2; G and H live here as half2

__device__ float2 g_G   [N_G];  // used as __half2[] for both G and H phases
__device__ float2 g_Ain [N_A];  // used as __half2[] (fp16 complex)
__device__ float2 g_Aout[N_A];  // used as __half2[] (fp16 complex)

typedef unsigned long long ull;

__device__ __forceinline__ ull pk2(float lo, float hi) {
    ull r; asm("mov.b64 %0, {%1,%2};" : "=l"(r) : "f"(lo), "f"(hi)); return r;
}
__device__ __forceinline__ float2 upk2(ull v) {
    float2 f; asm("mov.b64 {%0,%1}, %2;" : "=f"(f.x), "=f"(f.y) : "l"(v)); return f;
}

// ---------------------------------------------------------------------------
// FFT-64: radix-2 DIF, natural input -> bit-reversed output.
// ---------------------------------------------------------------------------
__constant__ float cW[32] = {
    1.0f, 0.99518472667f, 0.98078528040f, 0.95694033573f,
    0.92387953251f, 0.88192126435f, 0.83146961230f, 0.77301045336f,
    0.70710678119f, 0.63439328416f, 0.55557023302f, 0.47139673683f,
    0.38268343236f, 0.29028467725f, 0.19509032202f, 0.09801714033f,
    0.0f, -0.09801714033f, -0.19509032202f, -0.29028467725f,
    -0.38268343236f, -0.47139673683f, -0.55557023302f, -0.63439328416f,
    -0.70710678119f, -0.77301045336f, -0.83146961230f, -0.88192126435f,
    -0.92387953251f, -0.95694033573f, -0.98078528040f, -0.99518472667f };
__constant__ float sW[32] = {
    0.0f, 0.09801714033f, 0.19509032202f, 0.29028467725f,
    0.38268343236f, 0.47139673683f, 0.55557023302f, 0.63439328416f,
    0.70710678119f, 0.77301045336f, 0.83146961230f, 0.88192126435f,
    0.92387953251f, 0.95694033573f, 0.98078528040f, 0.99518472667f,
    1.0f, 0.99518472667f, 0.98078528040f, 0.95694033573f,
    0.92387953251f, 0.88192126435f, 0.83146961230f, 0.77301045336f,
    0.70710678119f, 0.63439328416f, 0.55557023302f, 0.47139673683f,
    0.38268343236f, 0.29028467725f, 0.19509032202f, 0.09801714033f };

__device__ __forceinline__ constexpr int bitrev6(int i) {
    return ((i & 1) << 5) | ((i & 2) << 3) | ((i & 4) << 1)
         | ((i & 8) >> 1) | ((i & 16) >> 3) | ((i & 32) >> 5);
}

template <int LEN, bool INV>
__device__ __forceinline__ void fft_stage(float2* x) {
    constexpr int HALF = LEN / 2;
    constexpr int STEP = 64 / LEN;
    #pragma unroll
    for (int st = 0; st < 64; st += LEN) {
        #pragma unroll
        for (int k = 0; k < HALF; k++) {
            float2 u = x[st + k], v = x[st + k + HALF];
            x[st + k] = make_float2(u.x + v.x, u.y + v.y);
            float2 t = make_float2(u.x - v.x, u.y - v.y);
            if (k == 0) {
                x[st + k + HALF] = t;
            } else {
                float wr = cW[k * STEP];
                float wi = INV ? sW[k * STEP] : -sW[k * STEP];
                x[st + k + HALF] = make_float2(t.x * wr - t.y * wi,
                                               t.x * wi + t.y * wr);
            }
        }
    }
}

template <bool INV>
__device__ __forceinline__ void fft64(float2* x) {
    fft_stage<64, INV>(x);
    fft_stage<32, INV>(x);
    fft_stage<16, INV>(x);
    fft_stage<8,  INV>(x);
    fft_stage<4,  INV>(x);
    fft_stage<2,  INV>(x);
}

// ---------------------------------------------------------------------------
// k1: forward FFT over phi. G[b,i,m,j,c] = X[(m-31)&63]/64, X = fft_p(f).
// G stored as half2 (fp16 complex). (R16-exact)
// ---------------------------------------------------------------------------
__global__ void k1_fft(const float* __restrict__ fre, const float* __restrict__ fim) {
    int bid = blockIdx.x;
    int j = bid & 63, bi = bid >> 6;
    int i = bi & 1,  b = bi >> 1;
    int c = threadIdx.x;   // 0..63

    long base = (long)(b * 64 + j) * 8192 + i * 64 + c;   // + p*128
    float2 x[64];
    #pragma unroll
    for (int p = 0; p < 64; p++) {
        long a = base + (long)p * 128;
        x[p] = make_float2(fre[a] * (1.0f / 64.0f), fim[a] * (1.0f / 64.0f));
    }
    fft64<false>(x);

    __half2* gG = (__half2*)g_G;
    long gb = (long)bi * 63 * 4096 + (long)j * 64 + c;
    #pragma unroll
    for (int r = 0; r < 64; r++) {
        int k = bitrev6(r);
        if (k != 32) {                       // m==63 bin doesn't exist
            int m = (k + 31) & 63;
            gG[gb + (long)m * 4096] = __floats2half2_rn(x[r].x, x[r].y);
        }
    }
}

// ---------------------------------------------------------------------------
// k2: theta quadrature on tensor cores (HMMA m16n8k16).
// A_in[l][ic] = sum_j P[l][j] * G[j][ic]  per (m,i,b):
//   M=32 (l), K=64 (j), N=128 real (64 complex c).
// sP[l][j] fp16 row-major (A operand); sG2[ic_real][j] (B operand, [n][k]).
// 8 warps: warp_m = wid&1 (2 m-tiles), warp_n = wid>>1 (4 n-groups of 32 real).
// ---------------------------------------------------------------------------
__global__ void k2_theta(const float* __restrict__ leg_in, const float* __restrict__ w) {
    __shared__ __half sP [32][66];    // [l][j], 66-half rows (33-word, odd)
    __shared__ __half sG2[128][66];   // [c_real][j]

    int m = blockIdx.x, i = blockIdx.y, b = blockIdx.z;
    int tid = threadIdx.x;
    int bi = b * 2 + i;
    int lmin = (m <= 31) ? (31 - m) : (m - 31);

    const __half2* gG = (const __half2*)g_G;
    long gbase = ((long)bi * 63 + m) * 4096;
    for (int e = tid; e < 4096; e += 256) {
        int j = e >> 6, c = e & 63;
        __half2 v = gG[gbase + (long)j * 64 + c];
        sG2[2 * c][j]     = __low2half(v);
        sG2[2 * c + 1][j] = __high2half(v);
    }
    for (int e = tid; e < 2048; e += 256) {
        int l = e >> 6, j = e & 63;
        float pl = TWO_PI_F * w[j] * leg_in[((i * 32 + l) * 63 + m) * 64 + j];
        sP[l][j] = __float2half(pl);
    }
    __syncthreads();

    int lane = tid & 31, wid = tid >> 5;
    int warp_m = wid & 1, warp_n = wid >> 1;
    int g = lane >> 2, tig = lane & 3;

    float acc[4][4];
    #pragma unroll
    for (int nt = 0; nt < 4; nt++)
        #pragma unroll
        for (int q = 0; q < 4; q++) acc[nt][q] = 0.0f;

    int ar = warp_m * 16 + g;
    #pragma unroll
    for (int kt = 0; kt < 4; kt++) {
        int kc = kt * 16 + tig * 2;
        unsigned int a0 = *(unsigned int*)&sP[ar][kc];
        unsigned int a1 = *(unsigned int*)&sP[ar + 8][kc];
        unsigned int a2 = *(unsigned int*)&sP[ar][kc + 8];
        unsigned int a3 = *(unsigned int*)&sP[ar + 8][kc + 8];
        #pragma unroll
        for (int nt = 0; nt < 4; nt++) {
            int bn = warp_n * 32 + nt * 8 + g;
            unsigned int b0 = *(unsigned int*)&sG2[bn][kc];
            unsigned int b1 = *(unsigned int*)&sG2[bn][kc + 8];
            asm volatile(
                "mma.sync.aligned.m16n8k16.row.col.f32.f16.f16.f32 "
                "{%0,%1,%2,%3}, {%4,%5,%6,%7}, {%8,%9}, {%0,%1,%2,%3};"
                : "+f"(acc[nt][0]), "+f"(acc[nt][1]),
                  "+f"(acc[nt][2]), "+f"(acc[nt][3])
                : "r"(a0), "r"(a1), "r"(a2), "r"(a3), "r"(b0), "r"(b1));
        }
    }

    __half2* gA = (__half2*)g_Ain;
    int l0 = warp_m * 16 + g, l1 = l0 + 8;
    #pragma unroll
    for (int nt = 0; nt < 4; nt++) {
        int d = warp_n * 16 + nt * 4 + tig;    // complex ic within 64
        if (l0 >= lmin) {
            long row = (long)(32 * l0 * l0) + b * (2 * l0 + 1) + (m - 31 + l0);
            gA[row * 128 + i * 64 + d] = __floats2half2_rn(acc[nt][0], acc[nt][1]);
        }
        if (l1 >= lmin) {
            long row = (long)(32 * l1 * l1) + b * (2 * l1 + 1) + (m - 31 + l1);
            gA[row * 128 + i * 64 + d] = __floats2half2_rn(acc[nt][2], acc[nt][3]);
        }
    }
}

// ---------------------------------------------------------------------------
// k3: per-l GEMM on tensor cores (R16-exact — passing).
// ---------------------------------------------------------------------------
__global__ void k3_gemm(const float* __restrict__ kre, const float* __restrict__ kim) {
    __shared__ __half sA[64][40];     // A tile: 64 rows x 32 real k (+8 pad)
    __shared__ __half sW2[128][40];   // W tile transposed: [n_real][k_real]

    int on = blockIdx.x, rt = blockIdx.y, l = blockIdx.z;
    if (rt > l) return;
    int nrow = 32 * (2 * l + 1);
    int row0 = rt * 64;

    int tid = threadIdx.x;
    int lane = tid & 31, wid = tid >> 5;
    int warp_m = wid & 3, warp_n = wid >> 2;
    int g = lane >> 2, tig = lane & 3;

    const __half2* gAin = (const __half2*)g_Ain;
    __half2* gAout = (__half2*)g_Aout;
    long Abase = (long)(32 * l * l) * 128;
    long wbase = (long)l * 16384 + (long)on * 4096;

    float acc[8][4];
    #pragma unroll
    for (int nt = 0; nt < 8; nt++)
        #pragma unroll
        for (int q = 0; q < 4; q++) acc[nt][q] = 0.0f;

    for (int it = 0; it < 8; it++) {
        int kc0 = it * 16;
        #pragma unroll
        for (int t = 0; t < 4; t++) {
            int idx = tid + t * 256;
            int rr = idx >> 4, cc = idx & 15;
            int grow = row0 + rr;
            __half2 v = __floats2half2_rn(0.0f, 0.0f);
            if (grow < nrow) v = gAin[Abase + (long)grow * 128 + kc0 + cc];
            *(__half2*)&sA[rr][cc * 2] = v;
        }
        #pragma unroll
        for (int t = 0; t < 4; t++) {
            int idx = tid + t * 256;
            int od_l = idx >> 4, ic_l = idx & 15;
            int ic = kc0 + ic_l;
            long a = wbase + (long)(ic >> 6) * 8192 + (ic & 63) * 64 + od_l;
            float kr = kre[a], ki = kim[a];
            *(__half2*)&sW2[od_l * 2][ic_l * 2]     = __floats2half2_rn(kr, -ki);
            *(__half2*)&sW2[od_l * 2 + 1][ic_l * 2] = __floats2half2_rn(ki, kr);
        }
        __syncthreads();

        int ar = warp_m * 16 + g;
        #pragma unroll
        for (int kt = 0; kt < 2; kt++) {
            int kc = kt * 16 + tig * 2;
            unsigned int a0 = *(unsigned int*)&sA[ar][kc];
            unsigned int a1 = *(unsigned int*)&sA[ar + 8][kc];
            unsigned int a2 = *(unsigned int*)&sA[ar][kc + 8];
            unsigned int a3 = *(unsigned int*)&sA[ar + 8][kc + 8];
            #pragma unroll
            for (int nt = 0; nt < 8; nt++) {
                int bn = warp_n * 64 + nt * 8 + g;
                unsigned int b0 = *(unsigned int*)&sW2[bn][kc];
                unsigned int b1 = *(unsigned int*)&sW2[bn][kc + 8];
                asm volatile(
                    "mma.sync.aligned.m16n8k16.row.col.f32.f16.f16.f32 "
                    "{%0,%1,%2,%3}, {%4,%5,%6,%7}, {%8,%9}, {%0,%1,%2,%3};"
                    : "+f"(acc[nt][0]), "+f"(acc[nt][1]),
                      "+f"(acc[nt][2]), "+f"(acc[nt][3])
                    : "r"(a0), "r"(a1), "r"(a2), "r"(a3), "r"(b0), "r"(b1));
            }
        }
        __syncthreads();
    }

    int grow0 = row0 + warp_m * 16 + g;
    int grow1 = grow0 + 8;
    #pragma unroll
    for (int nt = 0; nt < 8; nt++) {
        int od_l = warp_n * 32 + nt * 4 + tig;
        long colbase = Abase + (long)on * 64 + od_l;
        if (grow0 < nrow)
            gAout[colbase + (long)grow0 * 128] = __floats2half2_rn(acc[nt][0], acc[nt][1]);
        if (grow1 < nrow)
            gAout[colbase + (long)grow1 * 128] = __floats2half2_rn(acc[nt][2], acc[nt][3]);
    }
}

// ---------------------------------------------------------------------------
// k4: inverse theta on tensor cores (HMMA m16n8k16).
// H[j][d] = sum_l Q[l][j] * A_out[row(l,b,m-31+l)][d]  per (m,o,b):
//   M=64 (j), K=32 (l), N=128 real (64 complex d).
// sQ[j][l] fp16 row-major (A operand); sA2[d_real][l] (B operand).
// 8 warps: warp_m = wid&3 (4 m-tiles), warp_n = wid>>2 (2 n-groups of 64 real).
// ---------------------------------------------------------------------------
__global__ void k4_itheta(const float* __restrict__ leg_out) {
    __shared__ __half sQ [64][34];    // [j][l], 34-half rows (17-word, odd)
    __shared__ __half sA2[128][34];   // [d_real][l]

    int m = blockIdx.x, o = blockIdx.y, b = blockIdx.z;
    int tid = threadIdx.x;
    int lmin = (m <= 31) ? (31 - m) : (m - 31);

    const __half2* gAout = (const __half2*)g_Aout;
    for (int e = tid; e < 2048; e += 256) {
        int l = e >> 6, d = e & 63;
        __half2 v = __floats2half2_rn(0.0f, 0.0f);
        if (l >= lmin) {
            int mm = m - 31 + l;
            long row = (long)(32 * l * l) + b * (2 * l + 1) + mm;
            v = gAout[row * 128 + o * 64 + d];
        }
        sA2[2 * d][l]     = __low2half(v);
        sA2[2 * d + 1][l] = __high2half(v);
    }
    for (int e = tid; e < 2048; e += 256) {
        int l = e >> 6, j = e & 63;
        sQ[j][l] = __float2half(leg_out[((o * 32 + l) * 63 + m) * 64 + j]);
    }
    __syncthreads();

    int lane = tid & 31, wid = tid >> 5;
    int warp_m = wid & 3, warp_n = wid >> 2;
    int g = lane >> 2, tig = lane & 3;

    float acc[8][4];
    #pragma unroll
    for (int nt = 0; nt < 8; nt++)
        #pragma unroll
        for (int q = 0; q < 4; q++) acc[nt][q] = 0.0f;

    int ar = warp_m * 16 + g;
    #pragma unroll
    for (int kt = 0; kt < 2; kt++) {
        int kc = kt * 16 + tig * 2;
        unsigned int a0 = *(unsigned int*)&sQ[ar][kc];
        unsigned int a1 = *(unsigned int*)&sQ[ar + 8][kc];
        unsigned int a2 = *(unsigned int*)&sQ[ar][kc + 8];
        unsigned int a3 = *(unsigned int*)&sQ[ar + 8][kc + 8];
        #pragma unroll
        for (int nt = 0; nt < 8; nt++) {
            int bn = warp_n * 64 + nt * 8 + g;
            unsigned int b0 = *(unsigned int*)&sA2[bn][kc];
            unsigned int b1 = *(unsigned int*)&sA2[bn][kc + 8];
            asm volatile(
                "mma.sync.aligned.m16n8k16.row.col.f32.f16.f16.f32 "
                "{%0,%1,%2,%3}, {%4,%5,%6,%7}, {%8,%9}, {%0,%1,%2,%3};"
                : "+f"(acc[nt][0]), "+f"(acc[nt][1]),
                  "+f"(acc[nt][2]), "+f"(acc[nt][3])
                : "r"(a0), "r"(a1), "r"(a2), "r"(a3), "r"(b0), "r"(b1));
        }
    }

    __half2* gH = (__half2*)g_G;      // H region (fp16 complex), G is dead now
    int j0 = warp_m * 16 + g, j1 = j0 + 8;
    #pragma unroll
    for (int nt = 0; nt < 8; nt++) {
        int d = warp_n * 32 + nt * 4 + tig;    // complex d within 64
        gH[(long)((b * 64 + j0) * 2 + o) * 4032 + m * 64 + d] =
            __floats2half2_rn(acc[nt][0], acc[nt][1]);
        gH[(long)((b * 64 + j1) * 2 + o) * 4032 + m * 64 + d] =
            __floats2half2_rn(acc[nt][2], acc[nt][3]);
    }
}

// ---------------------------------------------------------------------------
// k5: inverse FFT over phi, H read as half2 (R16-exact).
// ---------------------------------------------------------------------------
__global__ void k5_ifft(void* __restrict__ dout, int mode, long out_cap) {
    int bid = blockIdx.x;             // matches k4's H layout
    int d = threadIdx.x;              // 0..63

    const __half2* gH = (const __half2*)g_G;
    long hb = (long)bid * 4032 + d;
    float2 x[64];
    #pragma unroll
    for (int k = 0; k < 64; k++) {
        if (k == 32) x[k] = make_float2(0.0f, 0.0f);
        else {
            int m = (k + 31) & 63;
            x[k] = __half22float2(gH[hb + (long)m * 64]);
        }
    }
    fft64<true>(x);

    int o = bid & 1;
    long bj = (long)(bid >> 1);
    if (mode == 1) {
        float2* out2 = (float2*)dout;
        #pragma unroll
        for (int r = 0; r < 64; r++) {
            int p = bitrev6(r);
            long oi = ((bj * 64 + p) * 2 + o) * 64 + d;
            if (oi < out_cap) out2[oi] = x[r];
        }
    } else {
        float* out1 = (float*)dout;
        #pragma unroll
        for (int r = 0; r < 64; r++) {
            int p = bitrev6(r);
            long oi = ((bj * 64 + p) * 2 + o) * 64 + d;
            if (oi < out_cap) out1[oi] = x[r].x;    // real part
        }
    }
}

// ---------------------------------------------------------------------------
// Host dispatch (identical to the passing R6-R16 logic).
// ---------------------------------------------------------------------------
extern "C" void kernel_launch(void* const* d_in, const int* in_sizes, int n_in,
                              void* d_out, int out_size) {
    if (n_in < 7) return;

    const float* sph[2] = {0, 0};
    const float* ker[2] = {0, 0};
    const float* leg[2] = {0, 0};
    const float* w = 0;
    int ns = 0, nk = 0, nl = 0;

    for (int t = 0; t < n_in; t++) {
        const float* p = (const float*)d_in[t];
        int sz = in_sizes[t];
        if (sz == SZ_SPHERE && ns < 2) sph[ns++] = p;
        else if (sz == SZ_KERNEL && nk < 2) ker[nk++] = p;
        else if (sz == SZ_LEG && nl < 2) leg[nl++] = p;
        else if (sz == SZ_W && !w) w = p;
    }
    if (ns != 2 || nk != 2 || nl != 2 || !w) return;

    bool alpha = (n_in == 7 &&
                  in_sizes[0] == SZ_KERNEL && in_sizes[1] == SZ_KERNEL &&
                  in_sizes[2] == SZ_LEG    && in_sizes[3] == SZ_LEG &&
                  in_sizes[4] == SZ_W      &&
                  in_sizes[5] == SZ_SPHERE && in_sizes[6] == SZ_SPHERE);

    const float *fre, *fim, *kre, *kim;
    if (alpha) { fim = sph[0]; fre = sph[1]; kim = ker[0]; kre = ker[1]; }
    else       { fre = sph[0]; fim = sph[1]; kre = ker[0]; kim = ker[1]; }
    const float* leg_in = leg[0];
    const float* leg_out = leg[1];

    int mode;
    long cap;
    if (out_size == 33554432)      { mode = 1; cap = 16777216; }   // float2 count
    else if (out_size == 16777216) { mode = 0; cap = 16777216; }   // float count
    else                           { mode = 0; cap = (long)out_size; }

    k1_fft   <<<4096, 64>>>(fre, fim);
    k2_theta <<<dim3(63, 2, 32), 256>>>(leg_in, w);
    k3_gemm  <<<dim3(2, 32, 32), 256>>>(kre, kim);
    k4_itheta<<<dim3(63, 2, 32), 256>>>(leg_out);
    k5_ifft  <<<4096, 64>>>(d_out, mode, cap);
}